// round 1
// baseline (speedup 1.0000x reference)
#include <cuda_runtime.h>
#include <math.h>

// ---------------------------------------------------------------------------
// Problem constants
// ---------------------------------------------------------------------------
#define BW      2048          // windows * batch
#define NTOK    98            // tokens per window (2*7*7)
#define DIM     256
#define NH      8
#define HD      32            // head dim
#define TBL     507           // (2*2-1)*(2*7-1)*(2*7-1)
#define HID     512           // cpb hidden
#define M_ROWS  (BW * NTOK)   // 200704

// ---------------------------------------------------------------------------
// Device scratch (no allocations allowed in kernel_launch)
// ---------------------------------------------------------------------------
// qkv laid out [3][BW][NH][NTOK][HD]
__device__ float g_qkv[3ull * BW * NH * NTOK * HD];   // ~616 MB
// attention output, [BW][NTOK][DIM]
__device__ float g_o[(size_t)BW * NTOK * DIM];        // ~205 MB
// cpb MLP output bt[TBL][NH]
__device__ float g_bt[TBL * NH];
// relative position bias rpb[NH][NTOK][NTOK]
__device__ float g_rpb[NH * NTOK * NTOK];

// ---------------------------------------------------------------------------
// Kernel 1: CPB MLP  bt[t][h] = sum_j relu(table[t]·w1[j] + b1[j]) * w2[h][j]
// ---------------------------------------------------------------------------
__device__ __forceinline__ float rel_coord(float x, float w) {
    float t = x / (w - 1.0f + 1e-6f) * 8.0f;
    float l = log2f(fabsf(t) + 1.0f) * (1.0f / 3.0f);   // log2(8)=3
    return (t > 0.0f) ? l : ((t < 0.0f) ? -l : 0.0f);
}

__global__ void cpb_mlp_kernel(const float* __restrict__ w1,   // [512,3]
                               const float* __restrict__ b1,   // [512]
                               const float* __restrict__ w2)   // [8,512]
{
    int t = blockIdx.x * blockDim.x + threadIdx.x;
    if (t >= TBL) return;
    int a = t / 169;          // 0..2   (depth rel, 2Wd-1 = 3)
    int b = (t / 13) % 13;    // 0..12
    int c = t % 13;           // 0..12
    float c0 = rel_coord((float)(a - 1), 2.0f);
    float c1 = rel_coord((float)(b - 6), 7.0f);
    float c2 = rel_coord((float)(c - 6), 7.0f);
    float acc[NH];
#pragma unroll
    for (int h = 0; h < NH; h++) acc[h] = 0.0f;
    for (int j = 0; j < HID; j++) {
        float hv = w1[j*3+0]*c0 + w1[j*3+1]*c1 + w1[j*3+2]*c2 + b1[j];
        hv = fmaxf(hv, 0.0f);
#pragma unroll
        for (int h = 0; h < NH; h++) acc[h] += hv * w2[h*HID + j];
    }
#pragma unroll
    for (int h = 0; h < NH; h++) g_bt[t*NH + h] = acc[h];
}

// ---------------------------------------------------------------------------
// Kernel 2: gather rpb[h][i][j] = 16*sigmoid(bt[idx(i,j)][h])
// ---------------------------------------------------------------------------
__global__ void rpb_kernel()
{
    int idx = blockIdx.x * blockDim.x + threadIdx.x;
    if (idx >= NH * NTOK * NTOK) return;
    int h = idx / (NTOK * NTOK);
    int r = idx % (NTOK * NTOK);
    int i = r / NTOK, j = r % NTOK;
    int di = i / 49, hi = (i / 7) % 7, wi = i % 7;
    int dj = j / 49, hj = (j / 7) % 7, wj = j % 7;
    int t = (di - dj + 1) * 169 + (hi - hj + 6) * 13 + (wi - wj + 6);
    float v = g_bt[t*NH + h];
    g_rpb[idx] = 16.0f / (1.0f + expf(-v));
}

// ---------------------------------------------------------------------------
// Kernel 3: QKV GEMM  C[m,n] = sum_k x[m,k] * qkv_w[n,k] + bias(n)
// 128x128x8 tiled fp32 SGEMM, output scattered to [3][BW][NH][NTOK][HD]
// ---------------------------------------------------------------------------
__global__ __launch_bounds__(256)
void sgemm_qkv_kernel(const float* __restrict__ A,   // [M_ROWS, 256]
                      const float* __restrict__ W,   // [768, 256]
                      const float* __restrict__ qb,  // [256]
                      const float* __restrict__ vb)  // [256]
{
    const int K = DIM;
    __shared__ float As[8][132];
    __shared__ float Bs[8][132];

    int bm = blockIdx.y * 128;
    int bn = blockIdx.x * 128;
    int tid = threadIdx.x;
    int tx = tid & 15;        // 0..15
    int ty = tid >> 4;        // 0..15

    float acc[8][8];
#pragma unroll
    for (int i = 0; i < 8; i++)
#pragma unroll
        for (int j = 0; j < 8; j++) acc[i][j] = 0.0f;

    int lrow = tid >> 1;          // 0..127
    int lk   = (tid & 1) * 4;     // 0 or 4
    const float* Aptr = A + (size_t)(bm + lrow) * K + lk;
    const float* Wptr = W + (size_t)(bn + lrow) * K + lk;

    for (int k0 = 0; k0 < K; k0 += 8) {
        float4 a4 = *(const float4*)(Aptr + k0);
        float4 b4 = *(const float4*)(Wptr + k0);
        As[lk+0][lrow] = a4.x; As[lk+1][lrow] = a4.y;
        As[lk+2][lrow] = a4.z; As[lk+3][lrow] = a4.w;
        Bs[lk+0][lrow] = b4.x; Bs[lk+1][lrow] = b4.y;
        Bs[lk+2][lrow] = b4.z; Bs[lk+3][lrow] = b4.w;
        __syncthreads();
#pragma unroll
        for (int kk = 0; kk < 8; kk++) {
            float ar[8], br[8];
            *(float4*)&ar[0] = *(const float4*)&As[kk][ty*8];
            *(float4*)&ar[4] = *(const float4*)&As[kk][ty*8+4];
            *(float4*)&br[0] = *(const float4*)&Bs[kk][tx*8];
            *(float4*)&br[4] = *(const float4*)&Bs[kk][tx*8+4];
#pragma unroll
            for (int i = 0; i < 8; i++)
#pragma unroll
                for (int j = 0; j < 8; j++)
                    acc[i][j] += ar[i] * br[j];
        }
        __syncthreads();
    }

    // scatter to g_qkv[which][b][h][tok][d]
#pragma unroll
    for (int i = 0; i < 8; i++) {
        int m = bm + ty*8 + i;
        int b = m / NTOK;
        int tok = m - b * NTOK;
#pragma unroll
        for (int j0 = 0; j0 < 8; j0 += 4) {
            int n = bn + tx*8 + j0;
            int which = n >> 8;           // 0=q 1=k 2=v
            int h = (n >> 5) & 7;
            int d = n & 31;
            float4 bias = make_float4(0.f, 0.f, 0.f, 0.f);
            if (which == 0)      bias = *(const float4*)(qb + (n & 255));
            else if (which == 2) bias = *(const float4*)(vb + (n & 255));
            float4 v4;
            v4.x = acc[i][j0+0] + bias.x;
            v4.y = acc[i][j0+1] + bias.y;
            v4.z = acc[i][j0+2] + bias.z;
            v4.w = acc[i][j0+3] + bias.w;
            size_t dst = (((size_t)which * BW + b) * NH + h) * (NTOK*HD)
                         + (size_t)tok * HD + d;
            *(float4*)(g_qkv + dst) = v4;
        }
    }
}

// ---------------------------------------------------------------------------
// Kernel 4: fused cosine attention per (window, head)
// smem: qs/ks/vs [98][36] + scores at [98][99]
// ---------------------------------------------------------------------------
#define QPAD 36
#define SPAD 99
#define ATTN_SMEM ((3 * NTOK * QPAD + NTOK * SPAD) * 4)

__global__ __launch_bounds__(128)
void attn_kernel(const float* __restrict__ logit_scale,  // [8]
                 float* __restrict__ o)                   // [BW, NTOK, DIM]
{
    extern __shared__ float sm[];
    float* qs = sm;
    float* ks = sm + NTOK * QPAD;
    float* vs = sm + 2 * NTOK * QPAD;
    float* at = sm + 3 * NTOK * QPAD;   // [98][99]

    int bh = blockIdx.x;
    int b = bh >> 3;
    int h = bh & 7;
    int tid = threadIdx.x;

    const size_t tensor_stride = (size_t)BW * NH * NTOK * HD;
    size_t base = ((size_t)b * NH + h) * (NTOK * HD);
    const float* Q = g_qkv + base;
    const float* Kp = g_qkv + tensor_stride + base;
    const float* Vp = g_qkv + 2 * tensor_stride + base;
    const float* rpb_h = g_rpb + (size_t)h * (NTOK * NTOK);

    // load q,k,v (padded) and rpb (into score buffer)
    for (int idx = tid; idx < NTOK * HD; idx += 128) {
        int r = idx >> 5, d = idx & 31;
        qs[r*QPAD + d] = Q[idx];
        ks[r*QPAD + d] = Kp[idx];
        vs[r*QPAD + d] = Vp[idx];
    }
    for (int idx = tid; idx < NTOK * NTOK; idx += 128) {
        int r = idx / NTOK, c = idx - r * NTOK;
        at[r*SPAD + c] = rpb_h[idx];
    }
    __syncthreads();

    float scale = expf(fminf(logit_scale[h], 4.6051702f));  // log(100)

    int i = tid;
    if (i < NTOK) {
        float nq = 0.f, nk = 0.f;
#pragma unroll
        for (int d = 0; d < HD; d++) {
            float q = qs[i*QPAD + d];
            float k = ks[i*QPAD + d];
            nq += q * q;
            nk += k * k;
        }
        float rq = scale / fmaxf(sqrtf(nq), 1e-12f);
        float rk = 1.0f / fmaxf(sqrtf(nk), 1e-12f);
#pragma unroll
        for (int d = 0; d < HD; d++) {
            qs[i*QPAD + d] *= rq;
            ks[i*QPAD + d] *= rk;
        }
    }
    __syncthreads();

    if (i < NTOK) {
        float qreg[HD];
#pragma unroll
        for (int d = 0; d < HD; d++) qreg[d] = qs[i*QPAD + d];

        float mx = -1e30f;
        for (int j = 0; j < NTOK; j++) {
            const float4* kr = (const float4*)(ks + j*QPAD);
            float s = 0.f;
#pragma unroll
            for (int c = 0; c < HD/4; c++) {
                float4 k4 = kr[c];
                s += qreg[c*4+0]*k4.x + qreg[c*4+1]*k4.y
                   + qreg[c*4+2]*k4.z + qreg[c*4+3]*k4.w;
            }
            s += at[i*SPAD + j];          // rpb
            at[i*SPAD + j] = s;
            mx = fmaxf(mx, s);
        }
        float sum = 0.f;
        for (int j = 0; j < NTOK; j++) {
            float e = expf(at[i*SPAD + j] - mx);
            at[i*SPAD + j] = e;
            sum += e;
        }
        float inv = 1.0f / sum;

        float accv[HD];
#pragma unroll
        for (int d = 0; d < HD; d++) accv[d] = 0.f;
        for (int j = 0; j < NTOK; j++) {
            float p = at[i*SPAD + j];
            const float4* vr = (const float4*)(vs + j*QPAD);
#pragma unroll
            for (int c = 0; c < HD/4; c++) {
                float4 v4 = vr[c];
                accv[c*4+0] += p * v4.x;
                accv[c*4+1] += p * v4.y;
                accv[c*4+2] += p * v4.z;
                accv[c*4+3] += p * v4.w;
            }
        }
        float* orow = o + ((size_t)b * NTOK + i) * DIM + h * HD;
#pragma unroll
        for (int c = 0; c < HD/4; c++) {
            float4 v4;
            v4.x = accv[c*4+0] * inv;
            v4.y = accv[c*4+1] * inv;
            v4.z = accv[c*4+2] * inv;
            v4.w = accv[c*4+3] * inv;
            *(float4*)(orow + c*4) = v4;
        }
    }
}

// ---------------------------------------------------------------------------
// Kernel 5: proj GEMM  out[m,n] = sum_k o[m,k]*proj_w[n,k] + proj_b[n]
// ---------------------------------------------------------------------------
__global__ __launch_bounds__(256)
void sgemm_proj_kernel(const float* __restrict__ A,    // g_o [M_ROWS,256]
                       const float* __restrict__ W,    // [256,256]
                       const float* __restrict__ bias, // [256]
                       float* __restrict__ C)          // [M_ROWS,256]
{
    const int K = DIM;
    __shared__ float As[8][132];
    __shared__ float Bs[8][132];

    int bm = blockIdx.y * 128;
    int bn = blockIdx.x * 128;
    int tid = threadIdx.x;
    int tx = tid & 15;
    int ty = tid >> 4;

    float acc[8][8];
#pragma unroll
    for (int i = 0; i < 8; i++)
#pragma unroll
        for (int j = 0; j < 8; j++) acc[i][j] = 0.0f;

    int lrow = tid >> 1;
    int lk   = (tid & 1) * 4;
    const float* Aptr = A + (size_t)(bm + lrow) * K + lk;
    const float* Wptr = W + (size_t)(bn + lrow) * K + lk;

    for (int k0 = 0; k0 < K; k0 += 8) {
        float4 a4 = *(const float4*)(Aptr + k0);
        float4 b4 = *(const float4*)(Wptr + k0);
        As[lk+0][lrow] = a4.x; As[lk+1][lrow] = a4.y;
        As[lk+2][lrow] = a4.z; As[lk+3][lrow] = a4.w;
        Bs[lk+0][lrow] = b4.x; Bs[lk+1][lrow] = b4.y;
        Bs[lk+2][lrow] = b4.z; Bs[lk+3][lrow] = b4.w;
        __syncthreads();
#pragma unroll
        for (int kk = 0; kk < 8; kk++) {
            float ar[8], br[8];
            *(float4*)&ar[0] = *(const float4*)&As[kk][ty*8];
            *(float4*)&ar[4] = *(const float4*)&As[kk][ty*8+4];
            *(float4*)&br[0] = *(const float4*)&Bs[kk][tx*8];
            *(float4*)&br[4] = *(const float4*)&Bs[kk][tx*8+4];
#pragma unroll
            for (int i = 0; i < 8; i++)
#pragma unroll
                for (int j = 0; j < 8; j++)
                    acc[i][j] += ar[i] * br[j];
        }
        __syncthreads();
    }

#pragma unroll
    for (int i = 0; i < 8; i++) {
        int m = bm + ty*8 + i;
#pragma unroll
        for (int j0 = 0; j0 < 8; j0 += 4) {
            int n = bn + tx*8 + j0;
            float4 bb = *(const float4*)(bias + n);
            float4 v4;
            v4.x = acc[i][j0+0] + bb.x;
            v4.y = acc[i][j0+1] + bb.y;
            v4.z = acc[i][j0+2] + bb.z;
            v4.w = acc[i][j0+3] + bb.w;
            *(float4*)(C + (size_t)m * DIM + n) = v4;
        }
    }
}

// ---------------------------------------------------------------------------
// kernel_launch
// ---------------------------------------------------------------------------
extern "C" void kernel_launch(void* const* d_in, const int* in_sizes, int n_in,
                              void* d_out, int out_size)
{
    const float* x           = (const float*)d_in[0];
    const float* qkv_w       = (const float*)d_in[1];
    const float* q_bias      = (const float*)d_in[2];
    const float* v_bias      = (const float*)d_in[3];
    const float* logit_scale = (const float*)d_in[4];
    const float* cpb_w1      = (const float*)d_in[5];
    const float* cpb_b1      = (const float*)d_in[6];
    const float* cpb_w2      = (const float*)d_in[7];
    const float* proj_w      = (const float*)d_in[8];
    const float* proj_b      = (const float*)d_in[9];
    float* out = (float*)d_out;

    // scratch pointer for attention output
    float* o_ptr = nullptr;
    cudaGetSymbolAddress((void**)&o_ptr, g_o);

    static bool attr_set = false;
    if (!attr_set) {
        cudaFuncSetAttribute(attn_kernel,
                             cudaFuncAttributeMaxDynamicSharedMemorySize,
                             ATTN_SMEM);
        attr_set = true;
    }

    // 1. CPB bias table
    cpb_mlp_kernel<<<(TBL + 127) / 128, 128>>>(cpb_w1, cpb_b1, cpb_w2);
    rpb_kernel<<<(NH * NTOK * NTOK + 255) / 256, 256>>>();

    // 2. QKV GEMM (M=200704, N=768, K=256)
    {
        dim3 grid(768 / 128, M_ROWS / 128);
        sgemm_qkv_kernel<<<grid, 256>>>(x, qkv_w, q_bias, v_bias);
    }

    // 3. fused attention: one block per (window, head)
    attn_kernel<<<BW * NH, 128, ATTN_SMEM>>>(logit_scale, o_ptr);

    // 4. proj GEMM (M=200704, N=256, K=256)
    {
        dim3 grid(DIM / 128, M_ROWS / 128);
        sgemm_proj_kernel<<<grid, 256>>>(o_ptr, proj_w, proj_b, out);
    }
}

// round 2
// speedup vs baseline: 1.0119x; 1.0119x over previous
#include <cuda_runtime.h>
#include <math.h>

// ---------------------------------------------------------------------------
// Problem constants
// ---------------------------------------------------------------------------
#define BW      2048
#define NTOK    98
#define DIM     256
#define NH      8
#define HD      32
#define TBL     507
#define HID     512
#define M_ROWS  (BW * NTOK)   // 200704

typedef unsigned long long ull;

// packed fp32x2 helpers (Blackwell FFMA2 — only reachable via PTX)
__device__ __forceinline__ ull ffma2(ull a, ull b, ull c) {
    ull d;
    asm("fma.rn.f32x2 %0, %1, %2, %3;" : "=l"(d) : "l"(a), "l"(b), "l"(c));
    return d;
}
__device__ __forceinline__ ull pack2(float x, float y) {
    ull r;
    asm("mov.b64 %0, {%1, %2};" : "=l"(r) : "f"(x), "f"(y));
    return r;
}
__device__ __forceinline__ float lo32(ull v) { return __uint_as_float((unsigned)v); }
__device__ __forceinline__ float hi32(ull v) { return __uint_as_float((unsigned)(v >> 32)); }

// ---------------------------------------------------------------------------
// Device scratch
// ---------------------------------------------------------------------------
__device__ float g_qkv[3ull * BW * NH * NTOK * HD];
__device__ float g_o[(size_t)BW * NTOK * DIM];
__device__ float g_bt[TBL * NH];
__device__ float g_rpb[NH * NTOK * NTOK];

// ---------------------------------------------------------------------------
// Kernel 1: CPB MLP
// ---------------------------------------------------------------------------
__device__ __forceinline__ float rel_coord(float x, float w) {
    float t = x / (w - 1.0f + 1e-6f) * 8.0f;
    float l = log2f(fabsf(t) + 1.0f) * (1.0f / 3.0f);
    return (t > 0.0f) ? l : ((t < 0.0f) ? -l : 0.0f);
}

__global__ void cpb_mlp_kernel(const float* __restrict__ w1,
                               const float* __restrict__ b1,
                               const float* __restrict__ w2)
{
    int t = blockIdx.x * blockDim.x + threadIdx.x;
    if (t >= TBL) return;
    int a = t / 169;
    int b = (t / 13) % 13;
    int c = t % 13;
    float c0 = rel_coord((float)(a - 1), 2.0f);
    float c1 = rel_coord((float)(b - 6), 7.0f);
    float c2 = rel_coord((float)(c - 6), 7.0f);
    float acc[NH];
#pragma unroll
    for (int h = 0; h < NH; h++) acc[h] = 0.0f;
    for (int j = 0; j < HID; j++) {
        float hv = w1[j*3+0]*c0 + w1[j*3+1]*c1 + w1[j*3+2]*c2 + b1[j];
        hv = fmaxf(hv, 0.0f);
#pragma unroll
        for (int h = 0; h < NH; h++) acc[h] += hv * w2[h*HID + j];
    }
#pragma unroll
    for (int h = 0; h < NH; h++) g_bt[t*NH + h] = acc[h];
}

// ---------------------------------------------------------------------------
// Kernel 2: rpb gather + sigmoid
// ---------------------------------------------------------------------------
__global__ void rpb_kernel()
{
    int idx = blockIdx.x * blockDim.x + threadIdx.x;
    if (idx >= NH * NTOK * NTOK) return;
    int h = idx / (NTOK * NTOK);
    int r = idx % (NTOK * NTOK);
    int i = r / NTOK, j = r % NTOK;
    int di = i / 49, hi = (i / 7) % 7, wi = i % 7;
    int dj = j / 49, hj = (j / 7) % 7, wj = j % 7;
    int t = (di - dj + 1) * 169 + (hi - hj + 6) * 13 + (wi - wj + 6);
    float v = g_bt[t*NH + h];
    g_rpb[idx] = 16.0f / (1.0f + __expf(-v));
}

// ---------------------------------------------------------------------------
// Kernel 3: QKV GEMM with FFMA2 (128x128 tile, 8x8 per thread)
// ---------------------------------------------------------------------------
__global__ __launch_bounds__(256)
void sgemm_qkv_kernel(const float* __restrict__ A,
                      const float* __restrict__ W,
                      const float* __restrict__ qb,
                      const float* __restrict__ vb)
{
    const int K = DIM;
    __shared__ __align__(16) float As2[8][264];  // A values duplicated into pairs
    __shared__ __align__(16) float Bs[8][132];

    int bm = blockIdx.y * 128;
    int bn = blockIdx.x * 128;
    int tid = threadIdx.x;
    int tx = tid & 15;
    int ty = tid >> 4;

    ull acc2[8][4];
#pragma unroll
    for (int i = 0; i < 8; i++)
#pragma unroll
        for (int j = 0; j < 4; j++) acc2[i][j] = 0ull;

    int lrow = tid >> 1;
    int lk   = (tid & 1) * 4;
    const float* Aptr = A + (size_t)(bm + lrow) * K + lk;
    const float* Wptr = W + (size_t)(bn + lrow) * K + lk;

    float4 a4 = *(const float4*)(Aptr);
    float4 b4 = *(const float4*)(Wptr);

    for (int k0 = 0; k0 < K; k0 += 8) {
        *(float2*)&As2[lk+0][2*lrow] = make_float2(a4.x, a4.x);
        *(float2*)&As2[lk+1][2*lrow] = make_float2(a4.y, a4.y);
        *(float2*)&As2[lk+2][2*lrow] = make_float2(a4.z, a4.z);
        *(float2*)&As2[lk+3][2*lrow] = make_float2(a4.w, a4.w);
        Bs[lk+0][lrow] = b4.x; Bs[lk+1][lrow] = b4.y;
        Bs[lk+2][lrow] = b4.z; Bs[lk+3][lrow] = b4.w;
        __syncthreads();
        if (k0 + 8 < K) {
            a4 = *(const float4*)(Aptr + k0 + 8);
            b4 = *(const float4*)(Wptr + k0 + 8);
        }
#pragma unroll
        for (int kk = 0; kk < 8; kk++) {
            ulonglong2 aa0 = *(const ulonglong2*)&As2[kk][ty*16 + 0];
            ulonglong2 aa1 = *(const ulonglong2*)&As2[kk][ty*16 + 4];
            ulonglong2 aa2 = *(const ulonglong2*)&As2[kk][ty*16 + 8];
            ulonglong2 aa3 = *(const ulonglong2*)&As2[kk][ty*16 + 12];
            ulonglong2 bb0 = *(const ulonglong2*)&Bs[kk][tx*8];
            ulonglong2 bb1 = *(const ulonglong2*)&Bs[kk][tx*8 + 4];
            ull av[8] = {aa0.x, aa0.y, aa1.x, aa1.y, aa2.x, aa2.y, aa3.x, aa3.y};
            ull bv[4] = {bb0.x, bb0.y, bb1.x, bb1.y};
#pragma unroll
            for (int i = 0; i < 8; i++)
#pragma unroll
                for (int jp = 0; jp < 4; jp++)
                    acc2[i][jp] = ffma2(av[i], bv[jp], acc2[i][jp]);
        }
        __syncthreads();
    }

    // scatter to g_qkv[which][b][h][tok][d]
#pragma unroll
    for (int i = 0; i < 8; i++) {
        int m = bm + ty*8 + i;
        int b = m / NTOK;
        int tok = m - b * NTOK;
#pragma unroll
        for (int jg = 0; jg < 2; jg++) {
            int n = bn + tx*8 + jg*4;
            int which = n >> 8;
            int h = (n >> 5) & 7;
            int d = n & 31;
            float4 bias = make_float4(0.f, 0.f, 0.f, 0.f);
            if (which == 0)      bias = *(const float4*)(qb + (n & 255));
            else if (which == 2) bias = *(const float4*)(vb + (n & 255));
            float4 v4;
            v4.x = lo32(acc2[i][jg*2+0]) + bias.x;
            v4.y = hi32(acc2[i][jg*2+0]) + bias.y;
            v4.z = lo32(acc2[i][jg*2+1]) + bias.z;
            v4.w = hi32(acc2[i][jg*2+1]) + bias.w;
            size_t dst = (((size_t)which * BW + b) * NH + h) * (NTOK*HD)
                         + (size_t)tok * HD + d;
            *(float4*)(g_qkv + dst) = v4;
        }
    }
}

// ---------------------------------------------------------------------------
// Kernel 4: fused cosine attention, packed math, q in registers
// smem: ks/vs [98][36] + scores [98][99]   (= 67 KB)
// ---------------------------------------------------------------------------
#define QPAD 36
#define SPAD 99
#define ATTN_SMEM ((2 * NTOK * QPAD + NTOK * SPAD) * 4)

__global__ __launch_bounds__(128)
void attn_kernel(const float* __restrict__ logit_scale,
                 float* __restrict__ o)
{
    extern __shared__ float sm[];
    float* ks = sm;
    float* vs = sm + NTOK * QPAD;
    float* at = sm + 2 * NTOK * QPAD;   // [98][99]

    int bh = blockIdx.x;
    int b = bh >> 3;
    int h = bh & 7;
    int tid = threadIdx.x;

    const size_t tensor_stride = (size_t)BW * NH * NTOK * HD;
    size_t base = ((size_t)b * NH + h) * (NTOK * HD);
    const float* Q  = g_qkv + base;
    const float* Kp = g_qkv + tensor_stride + base;
    const float* Vp = g_qkv + 2 * tensor_stride + base;
    const float* rpb_h = g_rpb + (size_t)h * (NTOK * NTOK);

    for (int idx = tid; idx < NTOK * HD; idx += 128) {
        int r = idx >> 5, d = idx & 31;
        ks[r*QPAD + d] = Kp[idx];
        vs[r*QPAD + d] = Vp[idx];
    }
    for (int idx = tid; idx < NTOK * NTOK; idx += 128) {
        int r = idx / NTOK, c = idx - r * NTOK;
        at[r*SPAD + c] = rpb_h[idx];
    }
    __syncthreads();

    float scale = __expf(fminf(logit_scale[h], 4.6051702f));

    int i = tid;
    ull q2[16];
    if (i < NTOK) {
        // q row -> registers, normalized * scale
        const float4* Qr = (const float4*)(Q + (size_t)i * HD);
        float qr[HD];
        float nq = 0.f;
#pragma unroll
        for (int c = 0; c < 8; c++) {
            float4 t = Qr[c];
            qr[c*4+0] = t.x; qr[c*4+1] = t.y; qr[c*4+2] = t.z; qr[c*4+3] = t.w;
            nq += t.x*t.x + t.y*t.y + t.z*t.z + t.w*t.w;
        }
        float rq = scale / fmaxf(sqrtf(nq), 1e-12f);
#pragma unroll
        for (int c = 0; c < 16; c++)
            q2[c] = pack2(qr[c*2] * rq, qr[c*2+1] * rq);

        // normalize k row i in smem
        float nk = 0.f;
#pragma unroll
        for (int d = 0; d < HD; d++) {
            float k = ks[i*QPAD + d];
            nk += k * k;
        }
        float rk = 1.0f / fmaxf(sqrtf(nk), 1e-12f);
#pragma unroll
        for (int c = 0; c < 8; c++) {
            float4 k4 = *(float4*)&ks[i*QPAD + c*4];
            k4.x *= rk; k4.y *= rk; k4.z *= rk; k4.w *= rk;
            *(float4*)&ks[i*QPAD + c*4] = k4;
        }
    }
    __syncthreads();

    if (i < NTOK) {
        // scores + max
        float mx = -1e30f;
        for (int j = 0; j < NTOK; j++) {
            const ulonglong2* kr = (const ulonglong2*)(ks + j*QPAD);
            ull s2a = 0ull, s2b = 0ull;
#pragma unroll
            for (int c = 0; c < 8; c += 2) {
                ulonglong2 ka = kr[c];
                ulonglong2 kb = kr[c+1];
                s2a = ffma2(q2[c*2+0], ka.x, s2a);
                s2b = ffma2(q2[c*2+1], ka.y, s2b);
                s2a = ffma2(q2[c*2+2], kb.x, s2a);
                s2b = ffma2(q2[c*2+3], kb.y, s2b);
            }
            float s = lo32(s2a) + hi32(s2a) + lo32(s2b) + hi32(s2b)
                    + at[i*SPAD + j];
            at[i*SPAD + j] = s;
            mx = fmaxf(mx, s);
        }
        // softmax
        float sum = 0.f;
        for (int j = 0; j < NTOK; j++) {
            float e = __expf(at[i*SPAD + j] - mx);
            at[i*SPAD + j] = e;
            sum += e;
        }
        float inv = 1.0f / sum;

        // PV
        ull accv2[16];
#pragma unroll
        for (int c = 0; c < 16; c++) accv2[c] = 0ull;
        for (int j = 0; j < NTOK; j++) {
            float p = at[i*SPAD + j];
            ull p2 = pack2(p, p);
            const ulonglong2* vr = (const ulonglong2*)(vs + j*QPAD);
#pragma unroll
            for (int c = 0; c < 8; c++) {
                ulonglong2 v2 = vr[c];
                accv2[c*2+0] = ffma2(p2, v2.x, accv2[c*2+0]);
                accv2[c*2+1] = ffma2(p2, v2.y, accv2[c*2+1]);
            }
        }
        float* orow = o + ((size_t)b * NTOK + i) * DIM + h * HD;
#pragma unroll
        for (int c = 0; c < 8; c++) {
            float4 v4;
            v4.x = lo32(accv2[c*2+0]) * inv;
            v4.y = hi32(accv2[c*2+0]) * inv;
            v4.z = lo32(accv2[c*2+1]) * inv;
            v4.w = hi32(accv2[c*2+1]) * inv;
            *(float4*)(orow + c*4) = v4;
        }
    }
}

// ---------------------------------------------------------------------------
// Kernel 5: proj GEMM with FFMA2
// ---------------------------------------------------------------------------
__global__ __launch_bounds__(256)
void sgemm_proj_kernel(const float* __restrict__ A,
                       const float* __restrict__ W,
                       const float* __restrict__ bias,
                       float* __restrict__ C)
{
    const int K = DIM;
    __shared__ __align__(16) float As2[8][264];
    __shared__ __align__(16) float Bs[8][132];

    int bm = blockIdx.y * 128;
    int bn = blockIdx.x * 128;
    int tid = threadIdx.x;
    int tx = tid & 15;
    int ty = tid >> 4;

    ull acc2[8][4];
#pragma unroll
    for (int i = 0; i < 8; i++)
#pragma unroll
        for (int j = 0; j < 4; j++) acc2[i][j] = 0ull;

    int lrow = tid >> 1;
    int lk   = (tid & 1) * 4;
    const float* Aptr = A + (size_t)(bm + lrow) * K + lk;
    const float* Wptr = W + (size_t)(bn + lrow) * K + lk;

    float4 a4 = *(const float4*)(Aptr);
    float4 b4 = *(const float4*)(Wptr);

    for (int k0 = 0; k0 < K; k0 += 8) {
        *(float2*)&As2[lk+0][2*lrow] = make_float2(a4.x, a4.x);
        *(float2*)&As2[lk+1][2*lrow] = make_float2(a4.y, a4.y);
        *(float2*)&As2[lk+2][2*lrow] = make_float2(a4.z, a4.z);
        *(float2*)&As2[lk+3][2*lrow] = make_float2(a4.w, a4.w);
        Bs[lk+0][lrow] = b4.x; Bs[lk+1][lrow] = b4.y;
        Bs[lk+2][lrow] = b4.z; Bs[lk+3][lrow] = b4.w;
        __syncthreads();
        if (k0 + 8 < K) {
            a4 = *(const float4*)(Aptr + k0 + 8);
            b4 = *(const float4*)(Wptr + k0 + 8);
        }
#pragma unroll
        for (int kk = 0; kk < 8; kk++) {
            ulonglong2 aa0 = *(const ulonglong2*)&As2[kk][ty*16 + 0];
            ulonglong2 aa1 = *(const ulonglong2*)&As2[kk][ty*16 + 4];
            ulonglong2 aa2 = *(const ulonglong2*)&As2[kk][ty*16 + 8];
            ulonglong2 aa3 = *(const ulonglong2*)&As2[kk][ty*16 + 12];
            ulonglong2 bb0 = *(const ulonglong2*)&Bs[kk][tx*8];
            ulonglong2 bb1 = *(const ulonglong2*)&Bs[kk][tx*8 + 4];
            ull av[8] = {aa0.x, aa0.y, aa1.x, aa1.y, aa2.x, aa2.y, aa3.x, aa3.y};
            ull bv[4] = {bb0.x, bb0.y, bb1.x, bb1.y};
#pragma unroll
            for (int i = 0; i < 8; i++)
#pragma unroll
                for (int jp = 0; jp < 4; jp++)
                    acc2[i][jp] = ffma2(av[i], bv[jp], acc2[i][jp]);
        }
        __syncthreads();
    }

#pragma unroll
    for (int i = 0; i < 8; i++) {
        int m = bm + ty*8 + i;
#pragma unroll
        for (int jg = 0; jg < 2; jg++) {
            int n = bn + tx*8 + jg*4;
            float4 bb = *(const float4*)(bias + n);
            float4 v4;
            v4.x = lo32(acc2[i][jg*2+0]) + bb.x;
            v4.y = hi32(acc2[i][jg*2+0]) + bb.y;
            v4.z = lo32(acc2[i][jg*2+1]) + bb.z;
            v4.w = hi32(acc2[i][jg*2+1]) + bb.w;
            *(float4*)(C + (size_t)m * DIM + n) = v4;
        }
    }
}

// ---------------------------------------------------------------------------
// kernel_launch
// ---------------------------------------------------------------------------
extern "C" void kernel_launch(void* const* d_in, const int* in_sizes, int n_in,
                              void* d_out, int out_size)
{
    const float* x           = (const float*)d_in[0];
    const float* qkv_w       = (const float*)d_in[1];
    const float* q_bias      = (const float*)d_in[2];
    const float* v_bias      = (const float*)d_in[3];
    const float* logit_scale = (const float*)d_in[4];
    const float* cpb_w1      = (const float*)d_in[5];
    const float* cpb_b1      = (const float*)d_in[6];
    const float* cpb_w2      = (const float*)d_in[7];
    const float* proj_w      = (const float*)d_in[8];
    const float* proj_b      = (const float*)d_in[9];
    float* out = (float*)d_out;

    float* o_ptr = nullptr;
    cudaGetSymbolAddress((void**)&o_ptr, g_o);

    static bool attr_set = false;
    if (!attr_set) {
        cudaFuncSetAttribute(attn_kernel,
                             cudaFuncAttributeMaxDynamicSharedMemorySize,
                             ATTN_SMEM);
        attr_set = true;
    }

    cpb_mlp_kernel<<<(TBL + 127) / 128, 128>>>(cpb_w1, cpb_b1, cpb_w2);
    rpb_kernel<<<(NH * NTOK * NTOK + 255) / 256, 256>>>();

    {
        dim3 grid(768 / 128, M_ROWS / 128);
        sgemm_qkv_kernel<<<grid, 256>>>(x, qkv_w, q_bias, v_bias);
    }

    attn_kernel<<<BW * NH, 128, ATTN_SMEM>>>(logit_scale, o_ptr);

    {
        dim3 grid(DIM / 128, M_ROWS / 128);
        sgemm_proj_kernel<<<grid, 256>>>(o_ptr, proj_w, proj_b, out);
    }
}

// round 4
// speedup vs baseline: 1.5484x; 1.5303x over previous
#include <cuda_runtime.h>
#include <cuda_bf16.h>
#include <math.h>
#include <stdint.h>

// ---------------------------------------------------------------------------
// Problem constants
// ---------------------------------------------------------------------------
#define BW      2048
#define NTOK    98
#define DIM     256
#define NH      8
#define HD      32
#define TBL     507
#define HID     512
#define M_ROWS  (BW * NTOK)    // 200704
#define MTILES  (M_ROWS / 128) // 1568

typedef unsigned long long ull;

// ---------------------------------------------------------------------------
// packed fp32x2 helpers (attention kernel)
// ---------------------------------------------------------------------------
__device__ __forceinline__ ull ffma2(ull a, ull b, ull c) {
    ull d;
    asm("fma.rn.f32x2 %0, %1, %2, %3;" : "=l"(d) : "l"(a), "l"(b), "l"(c));
    return d;
}
__device__ __forceinline__ ull pack2(float x, float y) {
    ull r;
    asm("mov.b64 %0, {%1, %2};" : "=l"(r) : "f"(x), "f"(y));
    return r;
}
__device__ __forceinline__ float lo32(ull v) { return __uint_as_float((unsigned)v); }
__device__ __forceinline__ float hi32(ull v) { return __uint_as_float((unsigned)(v >> 32)); }

// ---------------------------------------------------------------------------
// mma / ldmatrix helpers (arch-portable: sm_80+)
// ---------------------------------------------------------------------------
__device__ __forceinline__ uint32_t smem_u32(const void* p) {
    uint32_t a;
    asm("{ .reg .u64 t; cvta.to.shared.u64 t, %1; cvt.u32.u64 %0, t; }"
        : "=r"(a) : "l"(p));
    return a;
}

__device__ __forceinline__ void ldsm_x4(uint32_t* r, uint32_t addr) {
    asm volatile("ldmatrix.sync.aligned.m8n8.x4.shared.b16 {%0,%1,%2,%3}, [%4];"
                 : "=r"(r[0]), "=r"(r[1]), "=r"(r[2]), "=r"(r[3]) : "r"(addr));
}

__device__ __forceinline__ void mma16816(float* c, const uint32_t* a,
                                         uint32_t b0, uint32_t b1) {
    asm volatile("mma.sync.aligned.m16n8k16.row.col.f32.bf16.bf16.f32 "
                 "{%0,%1,%2,%3}, {%4,%5,%6,%7}, {%8,%9}, {%0,%1,%2,%3};"
                 : "+f"(c[0]), "+f"(c[1]), "+f"(c[2]), "+f"(c[3])
                 : "r"(a[0]), "r"(a[1]), "r"(a[2]), "r"(a[3]),
                   "r"(b0), "r"(b1));
}

// ---------------------------------------------------------------------------
// Device scratch
// ---------------------------------------------------------------------------
__device__ float g_qkv[3ull * BW * NH * NTOK * HD];
__device__ __nv_bfloat16 g_xh[(size_t)M_ROWS * DIM];
__device__ __nv_bfloat16 g_xl[(size_t)M_ROWS * DIM];
__device__ __nv_bfloat16 g_oh[(size_t)M_ROWS * DIM];
__device__ __nv_bfloat16 g_ol[(size_t)M_ROWS * DIM];
__device__ __nv_bfloat16 g_wqh[768 * DIM];
__device__ __nv_bfloat16 g_wql[768 * DIM];
__device__ __nv_bfloat16 g_wph[DIM * DIM];
__device__ __nv_bfloat16 g_wpl[DIM * DIM];
__device__ float g_bt[TBL * NH];
__device__ float g_rpb[NH * NTOK * NTOK];

// ---------------------------------------------------------------------------
// hi/lo bf16 split
// ---------------------------------------------------------------------------
__device__ __forceinline__ void split_bf16(float x, unsigned short& h, unsigned short& l) {
    __nv_bfloat16 hb = __float2bfloat16(x);
    float hf = __bfloat162float(hb);
    __nv_bfloat16 lb = __float2bfloat16(x - hf);
    h = __bfloat16_as_ushort(hb);
    l = __bfloat16_as_ushort(lb);
}

__global__ void cvt_hilo4(const float4* __restrict__ s,
                          uint2* __restrict__ dh, uint2* __restrict__ dl, int n4)
{
    int i = blockIdx.x * blockDim.x + threadIdx.x;
    if (i >= n4) return;
    float4 v = s[i];
    unsigned short h0,h1,h2,h3,l0,l1,l2,l3;
    split_bf16(v.x, h0, l0);
    split_bf16(v.y, h1, l1);
    split_bf16(v.z, h2, l2);
    split_bf16(v.w, h3, l3);
    uint2 H, L;
    H.x = (uint32_t)h0 | ((uint32_t)h1 << 16);
    H.y = (uint32_t)h2 | ((uint32_t)h3 << 16);
    L.x = (uint32_t)l0 | ((uint32_t)l1 << 16);
    L.y = (uint32_t)l2 | ((uint32_t)l3 << 16);
    dh[i] = H;
    dl[i] = L;
}

// ---------------------------------------------------------------------------
// CPB MLP + rpb
// ---------------------------------------------------------------------------
__device__ __forceinline__ float rel_coord(float x, float w) {
    float t = x / (w - 1.0f + 1e-6f) * 8.0f;
    float l = log2f(fabsf(t) + 1.0f) * (1.0f / 3.0f);
    return (t > 0.0f) ? l : ((t < 0.0f) ? -l : 0.0f);
}

__global__ void cpb_mlp_kernel(const float* __restrict__ w1,
                               const float* __restrict__ b1,
                               const float* __restrict__ w2)
{
    int t = blockIdx.x * blockDim.x + threadIdx.x;
    if (t >= TBL) return;
    int a = t / 169;
    int b = (t / 13) % 13;
    int c = t % 13;
    float c0 = rel_coord((float)(a - 1), 2.0f);
    float c1 = rel_coord((float)(b - 6), 7.0f);
    float c2 = rel_coord((float)(c - 6), 7.0f);
    float acc[NH];
#pragma unroll
    for (int h = 0; h < NH; h++) acc[h] = 0.0f;
    for (int j = 0; j < HID; j++) {
        float hv = w1[j*3+0]*c0 + w1[j*3+1]*c1 + w1[j*3+2]*c2 + b1[j];
        hv = fmaxf(hv, 0.0f);
#pragma unroll
        for (int h = 0; h < NH; h++) acc[h] += hv * w2[h*HID + j];
    }
#pragma unroll
    for (int h = 0; h < NH; h++) g_bt[t*NH + h] = acc[h];
}

__global__ void rpb_kernel()
{
    int idx = blockIdx.x * blockDim.x + threadIdx.x;
    if (idx >= NH * NTOK * NTOK) return;
    int h = idx / (NTOK * NTOK);
    int r = idx % (NTOK * NTOK);
    int i = r / NTOK, j = r % NTOK;
    int di = i / 49, hi = (i / 7) % 7, wi = i % 7;
    int dj = j / 49, hj = (j / 7) % 7, wj = j % 7;
    int t = (di - dj + 1) * 169 + (hi - hj + 6) * 13 + (wi - wj + 6);
    float v = g_bt[t*NH + h];
    g_rpb[idx] = 16.0f / (1.0f + __expf(-v));
}

// ---------------------------------------------------------------------------
// bf16x3 GEMM via mma.sync: C[128x128 tile] = A[Mx256] * B[Nx256]^T
// smem: 4 matrices (Ah, Al, Bh, Bl) x [128 rows x 32 cols bf16], padded rows
// ---------------------------------------------------------------------------
#define ROWB 80            // padded row stride in bytes (40 bf16)
#define MATB (128 * ROWB)  // 10240 bytes per matrix chunk

template<bool IS_QKV>
__global__ __launch_bounds__(256)
void gemm_mma(const __nv_bfloat16* __restrict__ Ah,
              const __nv_bfloat16* __restrict__ Al,
              const __nv_bfloat16* __restrict__ Bh,
              const __nv_bfloat16* __restrict__ Bl,
              float* __restrict__ outp,
              const float* __restrict__ qb,
              const float* __restrict__ vb,
              const float* __restrict__ pb)
{
    __shared__ __align__(16) unsigned char smc[4 * MATB];
    const uint32_t sb = smem_u32(smc);
    const uint32_t sAH = sb, sAL = sb + MATB, sBH = sb + 2*MATB, sBL = sb + 3*MATB;

    int tid  = threadIdx.x;
    int lane = tid & 31;
    int wid  = tid >> 5;
    int wm   = wid & 3;        // 4 m-groups of 32
    int wn   = wid >> 2;       // 2 n-groups of 64
    int m0   = blockIdx.y * 128;
    int n0   = blockIdx.x * 128;

    const uint4* pAh = (const uint4*)Ah;
    const uint4* pAl = (const uint4*)Al;
    const uint4* pBh = (const uint4*)Bh;
    const uint4* pBl = (const uint4*)Bl;

    // global-load mapping: 128 rows x 4 chunks(16B) per matrix; 2 chunks/thread
    int lr = tid >> 1;
    int lc = (tid & 1) * 2;
    size_t aIdx = (size_t)(m0 + lr) * 32 + lc;   // uint4 index, + k-chunk*4
    size_t bIdx = (size_t)(n0 + lr) * 32 + lc;
    uint32_t stoff = (uint32_t)lr * ROWB + (uint32_t)lc * 16;

    // ldmatrix base rows/chunks
    int a_row = wm*32 + (lane & 7) + ((lane >> 3) & 1) * 8;  // + mt*16
    int a_chk = (lane >> 4);                                  // + ks2*2
    int b_row = wn*64 + (lane & 7) + ((lane >> 4) & 1) * 8;  // + nn*16
    int b_chk = (lane >> 3) & 1;                              // + ks2*2

    float acc[2][8][4];
#pragma unroll
    for (int i = 0; i < 2; i++)
#pragma unroll
        for (int j = 0; j < 8; j++)
#pragma unroll
            for (int k = 0; k < 4; k++) acc[i][j][k] = 0.0f;

    // prefetch chunk 0
    uint4 rah0 = pAh[aIdx],     rah1 = pAh[aIdx + 1];
    uint4 ral0 = pAl[aIdx],     ral1 = pAl[aIdx + 1];
    uint4 rbh0 = pBh[bIdx],     rbh1 = pBh[bIdx + 1];
    uint4 rbl0 = pBl[bIdx],     rbl1 = pBl[bIdx + 1];

    for (int ck = 0; ck < 8; ck++) {
        // store prefetched chunk
        *(uint4*)(smc + 0*MATB + stoff)      = rah0;
        *(uint4*)(smc + 0*MATB + stoff + 16) = rah1;
        *(uint4*)(smc + 1*MATB + stoff)      = ral0;
        *(uint4*)(smc + 1*MATB + stoff + 16) = ral1;
        *(uint4*)(smc + 2*MATB + stoff)      = rbh0;
        *(uint4*)(smc + 2*MATB + stoff + 16) = rbh1;
        *(uint4*)(smc + 3*MATB + stoff)      = rbl0;
        *(uint4*)(smc + 3*MATB + stoff + 16) = rbl1;
        __syncthreads();

        // prefetch next chunk
        if (ck < 7) {
            size_t a2 = aIdx + (size_t)(ck + 1) * 4;
            size_t b2 = bIdx + (size_t)(ck + 1) * 4;
            rah0 = pAh[a2]; rah1 = pAh[a2 + 1];
            ral0 = pAl[a2]; ral1 = pAl[a2 + 1];
            rbh0 = pBh[b2]; rbh1 = pBh[b2 + 1];
            rbl0 = pBl[b2]; rbl1 = pBl[b2 + 1];
        }

        // compute on this chunk: two k16 steps
#pragma unroll
        for (int ks2 = 0; ks2 < 2; ks2++) {
            uint32_t ah[2][4], al[2][4];
#pragma unroll
            for (int mt = 0; mt < 2; mt++) {
                uint32_t off = (uint32_t)(a_row + mt*16) * ROWB
                             + (uint32_t)(a_chk + ks2*2) * 16;
                ldsm_x4(ah[mt], sAH + off);
                ldsm_x4(al[mt], sAL + off);
            }
            uint32_t bh[4][4], bl[4][4];
#pragma unroll
            for (int nn = 0; nn < 4; nn++) {
                uint32_t off = (uint32_t)(b_row + nn*16) * ROWB
                             + (uint32_t)(b_chk + ks2*2) * 16;
                ldsm_x4(bh[nn], sBH + off);
                ldsm_x4(bl[nn], sBL + off);
            }
#pragma unroll
            for (int mt = 0; mt < 2; mt++)
#pragma unroll
                for (int nt = 0; nt < 8; nt++) {
                    int pr = nt >> 1, w2 = (nt & 1) * 2;
                    mma16816(acc[mt][nt], ah[mt], bh[pr][w2], bh[pr][w2+1]);
                    mma16816(acc[mt][nt], ah[mt], bl[pr][w2], bl[pr][w2+1]);
                    mma16816(acc[mt][nt], al[mt], bh[pr][w2], bh[pr][w2+1]);
                }
        }
        __syncthreads();
    }

    // ---------------- epilogue ----------------
    const size_t tstride = (size_t)BW * NH * NTOK * HD;
#pragma unroll
    for (int mt = 0; mt < 2; mt++) {
        int rA = m0 + wm*32 + mt*16 + (lane >> 2);
#pragma unroll
        for (int nt = 0; nt < 8; nt++) {
            int n = n0 + wn*64 + nt*8 + (lane & 3) * 2;
            if (IS_QKV) {
                int which = n >> 8;
                int h = (n >> 5) & 7;
                int d = n & 31;
                float2 bv = make_float2(0.f, 0.f);
                if (which == 0)      bv = *(const float2*)(qb + (n & 255));
                else if (which == 2) bv = *(const float2*)(vb + (n & 255));
                // row rA
                {
                    int bwin = rA / NTOK, tok = rA - bwin * NTOK;
                    float* dst = g_qkv + (size_t)which * tstride
                               + (((size_t)bwin * NH + h) * NTOK + tok) * HD + d;
                    *(float2*)dst = make_float2(acc[mt][nt][0] + bv.x,
                                                acc[mt][nt][1] + bv.y);
                }
                // row rA + 8
                {
                    int r2 = rA + 8;
                    int bwin = r2 / NTOK, tok = r2 - bwin * NTOK;
                    float* dst = g_qkv + (size_t)which * tstride
                               + (((size_t)bwin * NH + h) * NTOK + tok) * HD + d;
                    *(float2*)dst = make_float2(acc[mt][nt][2] + bv.x,
                                                acc[mt][nt][3] + bv.y);
                }
            } else {
                float2 bv = *(const float2*)(pb + n);
                *(float2*)(outp + (size_t)rA * DIM + n) =
                    make_float2(acc[mt][nt][0] + bv.x, acc[mt][nt][1] + bv.y);
                *(float2*)(outp + (size_t)(rA + 8) * DIM + n) =
                    make_float2(acc[mt][nt][2] + bv.x, acc[mt][nt][3] + bv.y);
            }
        }
    }
}

// ---------------------------------------------------------------------------
// fused cosine attention (fp32 math, FFMA2) — writes bf16 hi/lo output
// ---------------------------------------------------------------------------
#define QPAD 36
#define SPAD 99
#define ATTN_SMEM ((2 * NTOK * QPAD + NTOK * SPAD) * 4)

__global__ __launch_bounds__(128)
void attn_kernel(const float* __restrict__ logit_scale)
{
    extern __shared__ float sm[];
    float* ks = sm;
    float* vs = sm + NTOK * QPAD;
    float* at = sm + 2 * NTOK * QPAD;

    int bh = blockIdx.x;
    int b = bh >> 3;
    int h = bh & 7;
    int tid = threadIdx.x;

    const size_t tensor_stride = (size_t)BW * NH * NTOK * HD;
    size_t base = ((size_t)b * NH + h) * (NTOK * HD);
    const float* Q  = g_qkv + base;
    const float* Kp = g_qkv + tensor_stride + base;
    const float* Vp = g_qkv + 2 * tensor_stride + base;
    const float* rpb_h = g_rpb + (size_t)h * (NTOK * NTOK);

    for (int idx = tid; idx < NTOK * HD; idx += 128) {
        int r = idx >> 5, d = idx & 31;
        ks[r*QPAD + d] = Kp[idx];
        vs[r*QPAD + d] = Vp[idx];
    }
    for (int idx = tid; idx < NTOK * NTOK; idx += 128) {
        int r = idx / NTOK, c = idx - r * NTOK;
        at[r*SPAD + c] = rpb_h[idx];
    }
    __syncthreads();

    float scale = __expf(fminf(logit_scale[h], 4.6051702f));

    int i = tid;
    ull q2[16];
    if (i < NTOK) {
        const float4* Qr = (const float4*)(Q + (size_t)i * HD);
        float qr[HD];
        float nq = 0.f;
#pragma unroll
        for (int c = 0; c < 8; c++) {
            float4 t = Qr[c];
            qr[c*4+0] = t.x; qr[c*4+1] = t.y; qr[c*4+2] = t.z; qr[c*4+3] = t.w;
            nq += t.x*t.x + t.y*t.y + t.z*t.z + t.w*t.w;
        }
        float rq = scale / fmaxf(sqrtf(nq), 1e-12f);
#pragma unroll
        for (int c = 0; c < 16; c++)
            q2[c] = pack2(qr[c*2] * rq, qr[c*2+1] * rq);

        float nk = 0.f;
#pragma unroll
        for (int d = 0; d < HD; d++) {
            float k = ks[i*QPAD + d];
            nk += k * k;
        }
        float rk = 1.0f / fmaxf(sqrtf(nk), 1e-12f);
#pragma unroll
        for (int c = 0; c < 8; c++) {
            float4 k4 = *(float4*)&ks[i*QPAD + c*4];
            k4.x *= rk; k4.y *= rk; k4.z *= rk; k4.w *= rk;
            *(float4*)&ks[i*QPAD + c*4] = k4;
        }
    }
    __syncthreads();

    if (i < NTOK) {
        float mx = -1e30f;
        for (int j = 0; j < NTOK; j++) {
            const ulonglong2* kr = (const ulonglong2*)(ks + j*QPAD);
            ull s2a = 0ull, s2b = 0ull;
#pragma unroll
            for (int c = 0; c < 8; c += 2) {
                ulonglong2 ka = kr[c];
                ulonglong2 kb = kr[c+1];
                s2a = ffma2(q2[c*2+0], ka.x, s2a);
                s2b = ffma2(q2[c*2+1], ka.y, s2b);
                s2a = ffma2(q2[c*2+2], kb.x, s2a);
                s2b = ffma2(q2[c*2+3], kb.y, s2b);
            }
            float s = lo32(s2a) + hi32(s2a) + lo32(s2b) + hi32(s2b)
                    + at[i*SPAD + j];
            at[i*SPAD + j] = s;
            mx = fmaxf(mx, s);
        }
        float sum = 0.f;
        for (int j = 0; j < NTOK; j++) {
            float e = __expf(at[i*SPAD + j] - mx);
            at[i*SPAD + j] = e;
            sum += e;
        }
        float inv = 1.0f / sum;

        ull accv2[16];
#pragma unroll
        for (int c = 0; c < 16; c++) accv2[c] = 0ull;
        for (int j = 0; j < NTOK; j++) {
            float p = at[i*SPAD + j];
            ull p2 = pack2(p, p);
            const ulonglong2* vr = (const ulonglong2*)(vs + j*QPAD);
#pragma unroll
            for (int c = 0; c < 8; c++) {
                ulonglong2 v2 = vr[c];
                accv2[c*2+0] = ffma2(p2, v2.x, accv2[c*2+0]);
                accv2[c*2+1] = ffma2(p2, v2.y, accv2[c*2+1]);
            }
        }
        size_t row = ((size_t)b * NTOK + i) * DIM + (size_t)h * HD;
        uint32_t* ohp = (uint32_t*)(g_oh + row);
        uint32_t* olp = (uint32_t*)(g_ol + row);
#pragma unroll
        for (int c = 0; c < 16; c++) {
            float v0 = lo32(accv2[c]) * inv;
            float v1 = hi32(accv2[c]) * inv;
            unsigned short h0, h1, l0, l1;
            split_bf16(v0, h0, l0);
            split_bf16(v1, h1, l1);
            ohp[c] = (uint32_t)h0 | ((uint32_t)h1 << 16);
            olp[c] = (uint32_t)l0 | ((uint32_t)l1 << 16);
        }
    }
}

// ---------------------------------------------------------------------------
// kernel_launch
// ---------------------------------------------------------------------------
extern "C" void kernel_launch(void* const* d_in, const int* in_sizes, int n_in,
                              void* d_out, int out_size)
{
    const float* x           = (const float*)d_in[0];
    const float* qkv_w       = (const float*)d_in[1];
    const float* q_bias      = (const float*)d_in[2];
    const float* v_bias      = (const float*)d_in[3];
    const float* logit_scale = (const float*)d_in[4];
    const float* cpb_w1      = (const float*)d_in[5];
    const float* cpb_b1      = (const float*)d_in[6];
    const float* cpb_w2      = (const float*)d_in[7];
    const float* proj_w      = (const float*)d_in[8];
    const float* proj_b      = (const float*)d_in[9];
    float* out = (float*)d_out;

    __nv_bfloat16 *xh, *xl, *oh, *ol, *wqh, *wql, *wph, *wpl;
    cudaGetSymbolAddress((void**)&xh,  g_xh);
    cudaGetSymbolAddress((void**)&xl,  g_xl);
    cudaGetSymbolAddress((void**)&oh,  g_oh);
    cudaGetSymbolAddress((void**)&ol,  g_ol);
    cudaGetSymbolAddress((void**)&wqh, g_wqh);
    cudaGetSymbolAddress((void**)&wql, g_wql);
    cudaGetSymbolAddress((void**)&wph, g_wph);
    cudaGetSymbolAddress((void**)&wpl, g_wpl);

    static bool attr_set = false;
    if (!attr_set) {
        cudaFuncSetAttribute(attn_kernel,
                             cudaFuncAttributeMaxDynamicSharedMemorySize, ATTN_SMEM);
        attr_set = true;
    }

    // 1. split inputs to bf16 hi/lo
    {
        int n4 = (M_ROWS * DIM) / 4;
        cvt_hilo4<<<(n4 + 255) / 256, 256>>>((const float4*)x, (uint2*)xh, (uint2*)xl, n4);
    }
    cvt_hilo4<<<(768 * DIM / 4 + 255) / 256, 256>>>((const float4*)qkv_w,
                                                    (uint2*)wqh, (uint2*)wql, 768 * DIM / 4);
    cvt_hilo4<<<(DIM * DIM / 4 + 255) / 256, 256>>>((const float4*)proj_w,
                                                    (uint2*)wph, (uint2*)wpl, DIM * DIM / 4);

    // 2. CPB bias
    cpb_mlp_kernel<<<(TBL + 127) / 128, 128>>>(cpb_w1, cpb_b1, cpb_w2);
    rpb_kernel<<<(NH * NTOK * NTOK + 255) / 256, 256>>>();

    // 3. QKV GEMM: M=200704, N=768 (6 n-tiles), K=256
    {
        dim3 grid(6, MTILES);
        gemm_mma<true><<<grid, 256>>>(xh, xl, wqh, wql,
                                      nullptr, q_bias, v_bias, nullptr);
    }

    // 4. fused attention (writes g_oh/g_ol)
    attn_kernel<<<BW * NH, 128, ATTN_SMEM>>>(logit_scale);

    // 5. proj GEMM: M=200704, N=256 (2 n-tiles), K=256
    {
        dim3 grid(2, MTILES);
        gemm_mma<false><<<grid, 256>>>(oh, ol, wph, wpl,
                                       out, nullptr, nullptr, proj_b);
    }
}

// round 5
// speedup vs baseline: 1.7238x; 1.1132x over previous
#include <cuda_runtime.h>
#include <cuda_bf16.h>
#include <math.h>
#include <stdint.h>

// ---------------------------------------------------------------------------
// Problem constants
// ---------------------------------------------------------------------------
#define BW      2048
#define NTOK    98
#define DIM     256
#define NH      8
#define HD      32
#define TBL     507
#define HID     512
#define M_ROWS  (BW * NTOK)    // 200704
#define MTILES  (M_ROWS / 128) // 1568

typedef unsigned long long ull;

// ---------------------------------------------------------------------------
// packed fp32x2 helpers (attention kernel)
// ---------------------------------------------------------------------------
__device__ __forceinline__ ull ffma2(ull a, ull b, ull c) {
    ull d;
    asm("fma.rn.f32x2 %0, %1, %2, %3;" : "=l"(d) : "l"(a), "l"(b), "l"(c));
    return d;
}
__device__ __forceinline__ ull pack2(float x, float y) {
    ull r;
    asm("mov.b64 %0, {%1, %2};" : "=l"(r) : "f"(x), "f"(y));
    return r;
}
__device__ __forceinline__ float lo32(ull v) { return __uint_as_float((unsigned)v); }
__device__ __forceinline__ float hi32(ull v) { return __uint_as_float((unsigned)(v >> 32)); }

// ---------------------------------------------------------------------------
// mma / ldmatrix / cp.async helpers (arch-portable: sm_80+)
// ---------------------------------------------------------------------------
__device__ __forceinline__ uint32_t smem_u32(const void* p) {
    uint32_t a;
    asm("{ .reg .u64 t; cvta.to.shared.u64 t, %1; cvt.u32.u64 %0, t; }"
        : "=r"(a) : "l"(p));
    return a;
}

__device__ __forceinline__ void ldsm_x4(uint32_t* r, uint32_t addr) {
    asm volatile("ldmatrix.sync.aligned.m8n8.x4.shared.b16 {%0,%1,%2,%3}, [%4];"
                 : "=r"(r[0]), "=r"(r[1]), "=r"(r[2]), "=r"(r[3]) : "r"(addr));
}

__device__ __forceinline__ void mma16816(float* c, const uint32_t* a,
                                         uint32_t b0, uint32_t b1) {
    asm volatile("mma.sync.aligned.m16n8k16.row.col.f32.bf16.bf16.f32 "
                 "{%0,%1,%2,%3}, {%4,%5,%6,%7}, {%8,%9}, {%0,%1,%2,%3};"
                 : "+f"(c[0]), "+f"(c[1]), "+f"(c[2]), "+f"(c[3])
                 : "r"(a[0]), "r"(a[1]), "r"(a[2]), "r"(a[3]),
                   "r"(b0), "r"(b1));
}

#define CP16(dst, src) \
    asm volatile("cp.async.cg.shared.global [%0], [%1], 16;" \
                 :: "r"(dst), "l"(src) : "memory")
#define CP_COMMIT() asm volatile("cp.async.commit_group;" ::: "memory")
#define CP_WAIT1()  asm volatile("cp.async.wait_group 1;" ::: "memory")
#define CP_WAIT0()  asm volatile("cp.async.wait_group 0;" ::: "memory")

// ---------------------------------------------------------------------------
// Device scratch
// ---------------------------------------------------------------------------
__device__ float g_qkv[3ull * BW * NH * NTOK * HD];
__device__ __nv_bfloat16 g_xh[(size_t)M_ROWS * DIM];
__device__ __nv_bfloat16 g_xl[(size_t)M_ROWS * DIM];
__device__ __nv_bfloat16 g_oh[(size_t)M_ROWS * DIM];
__device__ __nv_bfloat16 g_ol[(size_t)M_ROWS * DIM];
__device__ __nv_bfloat16 g_wqh[768 * DIM];
__device__ __nv_bfloat16 g_wql[768 * DIM];
__device__ __nv_bfloat16 g_wph[DIM * DIM];
__device__ __nv_bfloat16 g_wpl[DIM * DIM];
__device__ float g_bt[TBL * NH];
__device__ float g_rpb[NH * NTOK * NTOK];

// ---------------------------------------------------------------------------
// hi/lo bf16 split
// ---------------------------------------------------------------------------
__device__ __forceinline__ void split_bf16(float x, unsigned short& h, unsigned short& l) {
    __nv_bfloat16 hb = __float2bfloat16(x);
    float hf = __bfloat162float(hb);
    __nv_bfloat16 lb = __float2bfloat16(x - hf);
    h = __bfloat16_as_ushort(hb);
    l = __bfloat16_as_ushort(lb);
}

__global__ void cvt_hilo4(const float4* __restrict__ s,
                          uint2* __restrict__ dh, uint2* __restrict__ dl, int n4)
{
    int i = blockIdx.x * blockDim.x + threadIdx.x;
    if (i >= n4) return;
    float4 v = s[i];
    unsigned short h0,h1,h2,h3,l0,l1,l2,l3;
    split_bf16(v.x, h0, l0);
    split_bf16(v.y, h1, l1);
    split_bf16(v.z, h2, l2);
    split_bf16(v.w, h3, l3);
    uint2 H, L;
    H.x = (uint32_t)h0 | ((uint32_t)h1 << 16);
    H.y = (uint32_t)h2 | ((uint32_t)h3 << 16);
    L.x = (uint32_t)l0 | ((uint32_t)l1 << 16);
    L.y = (uint32_t)l2 | ((uint32_t)l3 << 16);
    dh[i] = H;
    dl[i] = L;
}

// ---------------------------------------------------------------------------
// CPB MLP — one warp per table entry
// ---------------------------------------------------------------------------
__device__ __forceinline__ float rel_coord(float x, float w) {
    float t = x / (w - 1.0f + 1e-6f) * 8.0f;
    float l = log2f(fabsf(t) + 1.0f) * (1.0f / 3.0f);
    return (t > 0.0f) ? l : ((t < 0.0f) ? -l : 0.0f);
}

__global__ void cpb_mlp_kernel(const float* __restrict__ w1,
                               const float* __restrict__ b1,
                               const float* __restrict__ w2)
{
    int gw = (blockIdx.x * blockDim.x + threadIdx.x) >> 5;
    int lane = threadIdx.x & 31;
    if (gw >= TBL) return;
    int a = gw / 169;
    int b = (gw / 13) % 13;
    int c = gw % 13;
    float c0 = rel_coord((float)(a - 1), 2.0f);
    float c1 = rel_coord((float)(b - 6), 7.0f);
    float c2 = rel_coord((float)(c - 6), 7.0f);
    float acc[NH];
#pragma unroll
    for (int h = 0; h < NH; h++) acc[h] = 0.0f;
    for (int j = lane; j < HID; j += 32) {
        float hv = w1[j*3+0]*c0 + w1[j*3+1]*c1 + w1[j*3+2]*c2 + b1[j];
        hv = fmaxf(hv, 0.0f);
#pragma unroll
        for (int h = 0; h < NH; h++) acc[h] += hv * w2[h*HID + j];
    }
#pragma unroll
    for (int h = 0; h < NH; h++) {
#pragma unroll
        for (int o = 16; o > 0; o >>= 1)
            acc[h] += __shfl_xor_sync(0xFFFFFFFFu, acc[h], o);
    }
    if (lane == 0) {
#pragma unroll
        for (int h = 0; h < NH; h++) g_bt[gw*NH + h] = acc[h];
    }
}

__global__ void rpb_kernel()
{
    int idx = blockIdx.x * blockDim.x + threadIdx.x;
    if (idx >= NH * NTOK * NTOK) return;
    int h = idx / (NTOK * NTOK);
    int r = idx % (NTOK * NTOK);
    int i = r / NTOK, j = r % NTOK;
    int di = i / 49, hi = (i / 7) % 7, wi = i % 7;
    int dj = j / 49, hj = (j / 7) % 7, wj = j % 7;
    int t = (di - dj + 1) * 169 + (hi - hj + 6) * 13 + (wi - wj + 6);
    float v = g_bt[t*NH + h];
    g_rpb[idx] = 16.0f / (1.0f + __expf(-v));
}

// ---------------------------------------------------------------------------
// A-resident bf16x3 GEMM via mma.sync + cp.async.
// CTA owns 128-row A tile (full K=256, hi+lo resident in smem) and loops
// nTiles n-tiles x 4 K64-chunks with double-buffered B.
// ---------------------------------------------------------------------------
#define AROW   528                 // padded A row stride bytes (264 bf16)
#define A_MAT  (128 * AROW)        // 67584
#define BROW   144                 // padded B row stride bytes (72 bf16)
#define B_MAT  (128 * BROW)        // 18432
#define OFF_B  (2 * A_MAT)         // 135168
#define GEMM_SMEM (2 * A_MAT + 4 * B_MAT)   // 208896

template<bool IS_QKV>
__global__ __launch_bounds__(256)
void gemm_mma(const __nv_bfloat16* __restrict__ Ah,
              const __nv_bfloat16* __restrict__ Al,
              const __nv_bfloat16* __restrict__ Bh,
              const __nv_bfloat16* __restrict__ Bl,
              float* __restrict__ outp,
              const float* __restrict__ qb,
              const float* __restrict__ vb,
              const float* __restrict__ pb,
              int nTiles)
{
    extern __shared__ __align__(16) unsigned char smc[];
    const uint32_t sb  = smem_u32(smc);
    const uint32_t sAH = sb;
    const uint32_t sAL = sb + A_MAT;

    int tid  = threadIdx.x;
    int lane = tid & 31;
    int wid  = tid >> 5;
    int wm   = wid & 3;        // 4 m-groups of 32
    int wn   = wid >> 2;       // 2 n-groups of 64
    int m0   = blockIdx.x * 128;
    int nIter = nTiles * 4;

    // ---- issue A loads (group 0, together with B chunk 0) ----
    {
        const char* gAh = (const char*)Ah + (size_t)m0 * 512;
        const char* gAl = (const char*)Al + (size_t)m0 * 512;
#pragma unroll
        for (int t = 0; t < 16; t++) {
            int cidx = tid + t * 256;          // 0..4095
            int r = cidx >> 5, c = cidx & 31;
            uint32_t so = (uint32_t)r * AROW + (uint32_t)c * 16;
            size_t  go = (size_t)r * 512 + (size_t)c * 16;
            CP16(sAH + so, gAh + go);
            CP16(sAL + so, gAl + go);
        }
    }
    // ---- B chunk issue helper (inlined via lambda-ish macro) ----
    auto issueB = [&](int it, int buf) {
        int nt = it >> 2, ck = it & 3;
        uint32_t bBH = sb + OFF_B + (uint32_t)buf * (2 * B_MAT);
        uint32_t bBL = bBH + B_MAT;
        const char* gBh = (const char*)Bh + (size_t)nt * 128 * 512 + (size_t)ck * 128;
        const char* gBl = (const char*)Bl + (size_t)nt * 128 * 512 + (size_t)ck * 128;
#pragma unroll
        for (int t = 0; t < 4; t++) {
            int cidx = tid + t * 256;          // 0..1023
            int r = cidx >> 3, c = cidx & 7;
            uint32_t so = (uint32_t)r * BROW + (uint32_t)c * 16;
            size_t  go = (size_t)r * 512 + (size_t)c * 16;
            CP16(bBH + so, gBh + go);
            CP16(bBL + so, gBl + go);
        }
    };

    issueB(0, 0);
    CP_COMMIT();            // group 0: A + B0
    issueB(1, 1);
    CP_COMMIT();            // group 1: B1
    CP_WAIT1();             // A + B0 complete
    __syncthreads();

    // ldmatrix base rows/chunks
    int a_row = wm*32 + (lane & 7) + ((lane >> 3) & 1) * 8;
    int a_chk = (lane >> 4);
    int b_row = wn*64 + (lane & 7) + ((lane >> 4) & 1) * 8;
    int b_chk = (lane >> 3) & 1;

    float acc[2][8][4];
#pragma unroll
    for (int i = 0; i < 2; i++)
#pragma unroll
        for (int j = 0; j < 8; j++)
#pragma unroll
            for (int k = 0; k < 4; k++) acc[i][j][k] = 0.0f;

    const size_t tstride = (size_t)BW * NH * NTOK * HD;

    for (int it = 0; it < nIter; it++) {
        int buf = it & 1;
        int ck  = it & 3;
        uint32_t bBH = sb + OFF_B + (uint32_t)buf * (2 * B_MAT);
        uint32_t bBL = bBH + B_MAT;

        // ---- compute 4 k16 steps on this chunk ----
#pragma unroll
        for (int kk = 0; kk < 4; kk++) {
            int kkg = ck * 4 + kk;
            uint32_t ah[2][4], al[2][4];
#pragma unroll
            for (int mt = 0; mt < 2; mt++) {
                uint32_t off = (uint32_t)(a_row + mt*16) * AROW
                             + (uint32_t)(a_chk + 2*kkg) * 16;
                ldsm_x4(ah[mt], sAH + off);
                ldsm_x4(al[mt], sAL + off);
            }
            uint32_t bh4[4][4], bl4[4][4];
#pragma unroll
            for (int nn = 0; nn < 4; nn++) {
                uint32_t off = (uint32_t)(b_row + nn*16) * BROW
                             + (uint32_t)(b_chk + 2*kk) * 16;
                ldsm_x4(bh4[nn], bBH + off);
                ldsm_x4(bl4[nn], bBL + off);
            }
#pragma unroll
            for (int mt = 0; mt < 2; mt++)
#pragma unroll
                for (int nt8 = 0; nt8 < 8; nt8++) {
                    int pr = nt8 >> 1, w2 = (nt8 & 1) * 2;
                    mma16816(acc[mt][nt8], ah[mt], bh4[pr][w2], bh4[pr][w2+1]);
                    mma16816(acc[mt][nt8], ah[mt], bl4[pr][w2], bl4[pr][w2+1]);
                    mma16816(acc[mt][nt8], al[mt], bh4[pr][w2], bh4[pr][w2+1]);
                }
        }

        // ---- epilogue when a full n-tile is done ----
        if (ck == 3) {
            int nt = it >> 2;
            int n0 = nt * 128;
#pragma unroll
            for (int mt = 0; mt < 2; mt++) {
                int rA = m0 + wm*32 + mt*16 + (lane >> 2);
#pragma unroll
                for (int nt8 = 0; nt8 < 8; nt8++) {
                    int n = n0 + wn*64 + nt8*8 + (lane & 3) * 2;
                    if (IS_QKV) {
                        int which = n >> 8;
                        int h = (n >> 5) & 7;
                        int d = n & 31;
                        float2 bv = make_float2(0.f, 0.f);
                        if (which == 0)      bv = *(const float2*)(qb + (n & 255));
                        else if (which == 2) bv = *(const float2*)(vb + (n & 255));
                        {
                            int bwin = rA / NTOK, tok = rA - bwin * NTOK;
                            float* dst = g_qkv + (size_t)which * tstride
                                       + (((size_t)bwin * NH + h) * NTOK + tok) * HD + d;
                            *(float2*)dst = make_float2(acc[mt][nt8][0] + bv.x,
                                                        acc[mt][nt8][1] + bv.y);
                        }
                        {
                            int r2 = rA + 8;
                            int bwin = r2 / NTOK, tok = r2 - bwin * NTOK;
                            float* dst = g_qkv + (size_t)which * tstride
                                       + (((size_t)bwin * NH + h) * NTOK + tok) * HD + d;
                            *(float2*)dst = make_float2(acc[mt][nt8][2] + bv.x,
                                                        acc[mt][nt8][3] + bv.y);
                        }
                    } else {
                        float2 bv = *(const float2*)(pb + n);
                        *(float2*)(outp + (size_t)rA * DIM + n) =
                            make_float2(acc[mt][nt8][0] + bv.x, acc[mt][nt8][1] + bv.y);
                        *(float2*)(outp + (size_t)(rA + 8) * DIM + n) =
                            make_float2(acc[mt][nt8][2] + bv.x, acc[mt][nt8][3] + bv.y);
                    }
                    acc[mt][nt8][0] = 0.f; acc[mt][nt8][1] = 0.f;
                    acc[mt][nt8][2] = 0.f; acc[mt][nt8][3] = 0.f;
                }
            }
        }

        if (it + 1 >= nIter) break;
        __syncthreads();                  // everyone done reading buf
        if (it + 2 < nIter) {
            issueB(it + 2, buf);          // refill the buffer just freed
            CP_COMMIT();
            CP_WAIT1();                   // B(it+1) complete
        } else {
            CP_WAIT0();                   // last chunk complete
        }
        __syncthreads();
    }
}

// ---------------------------------------------------------------------------
// fused cosine attention (fp32 math, FFMA2) — writes bf16 hi/lo output
// ---------------------------------------------------------------------------
#define QPAD 36
#define SPAD 99
#define ATTN_SMEM ((2 * NTOK * QPAD + NTOK * SPAD) * 4)

__global__ __launch_bounds__(128)
void attn_kernel(const float* __restrict__ logit_scale)
{
    extern __shared__ float sm[];
    float* ks = sm;
    float* vs = sm + NTOK * QPAD;
    float* at = sm + 2 * NTOK * QPAD;

    int bh = blockIdx.x;
    int b = bh >> 3;
    int h = bh & 7;
    int tid = threadIdx.x;

    const size_t tensor_stride = (size_t)BW * NH * NTOK * HD;
    size_t base = ((size_t)b * NH + h) * (NTOK * HD);
    const float* Q  = g_qkv + base;
    const float* Kp = g_qkv + tensor_stride + base;
    const float* Vp = g_qkv + 2 * tensor_stride + base;
    const float* rpb_h = g_rpb + (size_t)h * (NTOK * NTOK);

    for (int idx = tid; idx < NTOK * HD; idx += 128) {
        int r = idx >> 5, d = idx & 31;
        ks[r*QPAD + d] = Kp[idx];
        vs[r*QPAD + d] = Vp[idx];
    }
    for (int idx = tid; idx < NTOK * NTOK; idx += 128) {
        int r = idx / NTOK, c = idx - r * NTOK;
        at[r*SPAD + c] = rpb_h[idx];
    }
    __syncthreads();

    float scale = __expf(fminf(logit_scale[h], 4.6051702f));

    int i = tid;
    ull q2[16];
    if (i < NTOK) {
        const float4* Qr = (const float4*)(Q + (size_t)i * HD);
        float qr[HD];
        float nq = 0.f;
#pragma unroll
        for (int c = 0; c < 8; c++) {
            float4 t = Qr[c];
            qr[c*4+0] = t.x; qr[c*4+1] = t.y; qr[c*4+2] = t.z; qr[c*4+3] = t.w;
            nq += t.x*t.x + t.y*t.y + t.z*t.z + t.w*t.w;
        }
        float rq = scale / fmaxf(sqrtf(nq), 1e-12f);
#pragma unroll
        for (int c = 0; c < 16; c++)
            q2[c] = pack2(qr[c*2] * rq, qr[c*2+1] * rq);

        float nk = 0.f;
#pragma unroll
        for (int d = 0; d < HD; d++) {
            float k = ks[i*QPAD + d];
            nk += k * k;
        }
        float rk = 1.0f / fmaxf(sqrtf(nk), 1e-12f);
#pragma unroll
        for (int c = 0; c < 8; c++) {
            float4 k4 = *(float4*)&ks[i*QPAD + c*4];
            k4.x *= rk; k4.y *= rk; k4.z *= rk; k4.w *= rk;
            *(float4*)&ks[i*QPAD + c*4] = k4;
        }
    }
    __syncthreads();

    if (i < NTOK) {
        float mx = -1e30f;
        for (int j = 0; j < NTOK; j++) {
            const ulonglong2* kr = (const ulonglong2*)(ks + j*QPAD);
            ull s2a = 0ull, s2b = 0ull;
#pragma unroll
            for (int c = 0; c < 8; c += 2) {
                ulonglong2 ka = kr[c];
                ulonglong2 kb = kr[c+1];
                s2a = ffma2(q2[c*2+0], ka.x, s2a);
                s2b = ffma2(q2[c*2+1], ka.y, s2b);
                s2a = ffma2(q2[c*2+2], kb.x, s2a);
                s2b = ffma2(q2[c*2+3], kb.y, s2b);
            }
            float s = lo32(s2a) + hi32(s2a) + lo32(s2b) + hi32(s2b)
                    + at[i*SPAD + j];
            at[i*SPAD + j] = s;
            mx = fmaxf(mx, s);
        }
        float sum = 0.f;
        for (int j = 0; j < NTOK; j++) {
            float e = __expf(at[i*SPAD + j] - mx);
            at[i*SPAD + j] = e;
            sum += e;
        }
        float inv = 1.0f / sum;

        ull accv2[16];
#pragma unroll
        for (int c = 0; c < 16; c++) accv2[c] = 0ull;
        for (int j = 0; j < NTOK; j++) {
            float p = at[i*SPAD + j];
            ull p2 = pack2(p, p);
            const ulonglong2* vr = (const ulonglong2*)(vs + j*QPAD);
#pragma unroll
            for (int c = 0; c < 8; c++) {
                ulonglong2 v2 = vr[c];
                accv2[c*2+0] = ffma2(p2, v2.x, accv2[c*2+0]);
                accv2[c*2+1] = ffma2(p2, v2.y, accv2[c*2+1]);
            }
        }
        size_t row = ((size_t)b * NTOK + i) * DIM + (size_t)h * HD;
        uint32_t* ohp = (uint32_t*)(g_oh + row);
        uint32_t* olp = (uint32_t*)(g_ol + row);
#pragma unroll
        for (int c = 0; c < 16; c++) {
            float v0 = lo32(accv2[c]) * inv;
            float v1 = hi32(accv2[c]) * inv;
            unsigned short h0, h1, l0, l1;
            split_bf16(v0, h0, l0);
            split_bf16(v1, h1, l1);
            ohp[c] = (uint32_t)h0 | ((uint32_t)h1 << 16);
            olp[c] = (uint32_t)l0 | ((uint32_t)l1 << 16);
        }
    }
}

// ---------------------------------------------------------------------------
// kernel_launch
// ---------------------------------------------------------------------------
extern "C" void kernel_launch(void* const* d_in, const int* in_sizes, int n_in,
                              void* d_out, int out_size)
{
    const float* x           = (const float*)d_in[0];
    const float* qkv_w       = (const float*)d_in[1];
    const float* q_bias      = (const float*)d_in[2];
    const float* v_bias      = (const float*)d_in[3];
    const float* logit_scale = (const float*)d_in[4];
    const float* cpb_w1      = (const float*)d_in[5];
    const float* cpb_b1      = (const float*)d_in[6];
    const float* cpb_w2      = (const float*)d_in[7];
    const float* proj_w      = (const float*)d_in[8];
    const float* proj_b      = (const float*)d_in[9];
    float* out = (float*)d_out;

    __nv_bfloat16 *xh, *xl, *oh, *ol, *wqh, *wql, *wph, *wpl;
    cudaGetSymbolAddress((void**)&xh,  g_xh);
    cudaGetSymbolAddress((void**)&xl,  g_xl);
    cudaGetSymbolAddress((void**)&oh,  g_oh);
    cudaGetSymbolAddress((void**)&ol,  g_ol);
    cudaGetSymbolAddress((void**)&wqh, g_wqh);
    cudaGetSymbolAddress((void**)&wql, g_wql);
    cudaGetSymbolAddress((void**)&wph, g_wph);
    cudaGetSymbolAddress((void**)&wpl, g_wpl);

    static bool attr_set = false;
    if (!attr_set) {
        cudaFuncSetAttribute(attn_kernel,
                             cudaFuncAttributeMaxDynamicSharedMemorySize, ATTN_SMEM);
        cudaFuncSetAttribute(gemm_mma<true>,
                             cudaFuncAttributeMaxDynamicSharedMemorySize, GEMM_SMEM);
        cudaFuncSetAttribute(gemm_mma<false>,
                             cudaFuncAttributeMaxDynamicSharedMemorySize, GEMM_SMEM);
        attr_set = true;
    }

    // 1. split inputs to bf16 hi/lo
    {
        int n4 = (M_ROWS * DIM) / 4;
        cvt_hilo4<<<(n4 + 255) / 256, 256>>>((const float4*)x, (uint2*)xh, (uint2*)xl, n4);
    }
    cvt_hilo4<<<(768 * DIM / 4 + 255) / 256, 256>>>((const float4*)qkv_w,
                                                    (uint2*)wqh, (uint2*)wql, 768 * DIM / 4);
    cvt_hilo4<<<(DIM * DIM / 4 + 255) / 256, 256>>>((const float4*)proj_w,
                                                    (uint2*)wph, (uint2*)wpl, DIM * DIM / 4);

    // 2. CPB bias (warp-per-entry)
    cpb_mlp_kernel<<<(TBL * 32 + 255) / 256, 256>>>(cpb_w1, cpb_b1, cpb_w2);
    rpb_kernel<<<(NH * NTOK * NTOK + 255) / 256, 256>>>();

    // 3. QKV GEMM: M=200704 (1568 CTAs), N=768 (6 inner n-tiles), K=256
    gemm_mma<true><<<MTILES, 256, GEMM_SMEM>>>(xh, xl, wqh, wql,
                                               nullptr, q_bias, v_bias, nullptr, 6);

    // 4. fused attention (writes g_oh/g_ol)
    attn_kernel<<<BW * NH, 128, ATTN_SMEM>>>(logit_scale);

    // 5. proj GEMM: N=256 (2 inner n-tiles)
    gemm_mma<false><<<MTILES, 256, GEMM_SMEM>>>(oh, ol, wph, wpl,
                                                out, nullptr, nullptr, proj_b, 2);
}

// round 6
// speedup vs baseline: 1.8874x; 1.0949x over previous
#include <cuda_runtime.h>
#include <cuda_bf16.h>
#include <math.h>
#include <stdint.h>

// ---------------------------------------------------------------------------
// Problem constants
// ---------------------------------------------------------------------------
#define BW      2048
#define NTOK    98
#define DIM     256
#define NH      8
#define HD      32
#define TBL     507
#define HID     512
#define M_ROWS  (BW * NTOK)    // 200704
#define MTILES  (M_ROWS / 128) // 1568

typedef unsigned long long ull;

// ---------------------------------------------------------------------------
// packed fp32x2 helpers
// ---------------------------------------------------------------------------
__device__ __forceinline__ ull ffma2(ull a, ull b, ull c) {
    ull d;
    asm("fma.rn.f32x2 %0, %1, %2, %3;" : "=l"(d) : "l"(a), "l"(b), "l"(c));
    return d;
}
__device__ __forceinline__ ull pack2(float x, float y) {
    ull r;
    asm("mov.b64 %0, {%1, %2};" : "=l"(r) : "f"(x), "f"(y));
    return r;
}
__device__ __forceinline__ float lo32(ull v) { return __uint_as_float((unsigned)v); }
__device__ __forceinline__ float hi32(ull v) { return __uint_as_float((unsigned)(v >> 32)); }

// ---------------------------------------------------------------------------
// mma / ldmatrix / cp.async helpers (arch-portable: sm_80+)
// ---------------------------------------------------------------------------
__device__ __forceinline__ uint32_t smem_u32(const void* p) {
    uint32_t a;
    asm("{ .reg .u64 t; cvta.to.shared.u64 t, %1; cvt.u32.u64 %0, t; }"
        : "=r"(a) : "l"(p));
    return a;
}

__device__ __forceinline__ void ldsm_x4(uint32_t* r, uint32_t addr) {
    asm volatile("ldmatrix.sync.aligned.m8n8.x4.shared.b16 {%0,%1,%2,%3}, [%4];"
                 : "=r"(r[0]), "=r"(r[1]), "=r"(r[2]), "=r"(r[3]) : "r"(addr));
}

__device__ __forceinline__ void mma16816(float* c, const uint32_t* a,
                                         uint32_t b0, uint32_t b1) {
    asm volatile("mma.sync.aligned.m16n8k16.row.col.f32.bf16.bf16.f32 "
                 "{%0,%1,%2,%3}, {%4,%5,%6,%7}, {%8,%9}, {%0,%1,%2,%3};"
                 : "+f"(c[0]), "+f"(c[1]), "+f"(c[2]), "+f"(c[3])
                 : "r"(a[0]), "r"(a[1]), "r"(a[2]), "r"(a[3]),
                   "r"(b0), "r"(b1));
}

#define CP16(dst, src) \
    asm volatile("cp.async.cg.shared.global [%0], [%1], 16;" \
                 :: "r"(dst), "l"(src) : "memory")
#define CP_COMMIT() asm volatile("cp.async.commit_group;" ::: "memory")
#define CP_WAIT1()  asm volatile("cp.async.wait_group 1;" ::: "memory")
#define CP_WAIT0()  asm volatile("cp.async.wait_group 0;" ::: "memory")

// ---------------------------------------------------------------------------
// Device scratch
// ---------------------------------------------------------------------------
__device__ float g_qkv[3ull * BW * NH * NTOK * HD];
__device__ __nv_bfloat16 g_xh[(size_t)M_ROWS * DIM];
__device__ __nv_bfloat16 g_xl[(size_t)M_ROWS * DIM];
__device__ __nv_bfloat16 g_oh[(size_t)M_ROWS * DIM];
__device__ __nv_bfloat16 g_ol[(size_t)M_ROWS * DIM];
__device__ __nv_bfloat16 g_wqh[768 * DIM];
__device__ __nv_bfloat16 g_wql[768 * DIM];
__device__ __nv_bfloat16 g_wph[DIM * DIM];
__device__ __nv_bfloat16 g_wpl[DIM * DIM];
__device__ float g_bt[TBL * NH];
__device__ float g_rpbT[NH * NTOK * NTOK];   // TRANSPOSED: [h][j(key)][i(query)]

// ---------------------------------------------------------------------------
// hi/lo bf16 split
// ---------------------------------------------------------------------------
__device__ __forceinline__ void split_bf16(float x, unsigned short& h, unsigned short& l) {
    __nv_bfloat16 hb = __float2bfloat16(x);
    float hf = __bfloat162float(hb);
    __nv_bfloat16 lb = __float2bfloat16(x - hf);
    h = __bfloat16_as_ushort(hb);
    l = __bfloat16_as_ushort(lb);
}

__global__ void cvt_hilo4(const float4* __restrict__ s,
                          uint2* __restrict__ dh, uint2* __restrict__ dl, int n4)
{
    int i = blockIdx.x * blockDim.x + threadIdx.x;
    if (i >= n4) return;
    float4 v = s[i];
    unsigned short h0,h1,h2,h3,l0,l1,l2,l3;
    split_bf16(v.x, h0, l0);
    split_bf16(v.y, h1, l1);
    split_bf16(v.z, h2, l2);
    split_bf16(v.w, h3, l3);
    uint2 H, L;
    H.x = (uint32_t)h0 | ((uint32_t)h1 << 16);
    H.y = (uint32_t)h2 | ((uint32_t)h3 << 16);
    L.x = (uint32_t)l0 | ((uint32_t)l1 << 16);
    L.y = (uint32_t)l2 | ((uint32_t)l3 << 16);
    dh[i] = H;
    dl[i] = L;
}

// ---------------------------------------------------------------------------
// CPB MLP — 8 warps/block, weights staged in smem
// ---------------------------------------------------------------------------
__device__ __forceinline__ float rel_coord(float x, float w) {
    float t = x / (w - 1.0f + 1e-6f) * 8.0f;
    float l = log2f(fabsf(t) + 1.0f) * (1.0f / 3.0f);
    return (t > 0.0f) ? l : ((t < 0.0f) ? -l : 0.0f);
}

__global__ __launch_bounds__(256)
void cpb_mlp_kernel(const float* __restrict__ w1,
                    const float* __restrict__ b1,
                    const float* __restrict__ w2)
{
    __shared__ float s_w1[HID * 3];
    __shared__ float s_b1[HID];
    __shared__ float s_w2[NH * HID];

    int tid = threadIdx.x;
    for (int i = tid; i < HID * 3; i += 256) s_w1[i] = w1[i];
    for (int i = tid; i < HID; i += 256)     s_b1[i] = b1[i];
    for (int i = tid; i < NH * HID; i += 256) s_w2[i] = w2[i];
    __syncthreads();

    int gw = blockIdx.x * 8 + (tid >> 5);
    int lane = tid & 31;
    if (gw >= TBL) return;
    int a = gw / 169;
    int b = (gw / 13) % 13;
    int c = gw % 13;
    float c0 = rel_coord((float)(a - 1), 2.0f);
    float c1 = rel_coord((float)(b - 6), 7.0f);
    float c2 = rel_coord((float)(c - 6), 7.0f);
    float acc[NH];
#pragma unroll
    for (int h = 0; h < NH; h++) acc[h] = 0.0f;
    for (int j = lane; j < HID; j += 32) {
        float hv = s_w1[j*3+0]*c0 + s_w1[j*3+1]*c1 + s_w1[j*3+2]*c2 + s_b1[j];
        hv = fmaxf(hv, 0.0f);
#pragma unroll
        for (int h = 0; h < NH; h++) acc[h] += hv * s_w2[h*HID + j];
    }
#pragma unroll
    for (int h = 0; h < NH; h++) {
#pragma unroll
        for (int o = 16; o > 0; o >>= 1)
            acc[h] += __shfl_xor_sync(0xFFFFFFFFu, acc[h], o);
    }
    if (lane == 0) {
#pragma unroll
        for (int h = 0; h < NH; h++) g_bt[gw*NH + h] = acc[h];
    }
}

// rpb gather — writes TRANSPOSED layout [h][j][i]
__global__ void rpb_kernel()
{
    int idx = blockIdx.x * blockDim.x + threadIdx.x;
    if (idx >= NH * NTOK * NTOK) return;
    int h = idx / (NTOK * NTOK);
    int r = idx % (NTOK * NTOK);
    int j = r / NTOK, i = r % NTOK;       // output index (h, j, i); value from (i=query, j=key)
    int di = i / 49, hi = (i / 7) % 7, wi = i % 7;
    int dj = j / 49, hj = (j / 7) % 7, wj = j % 7;
    int t = (di - dj + 1) * 169 + (hi - hj + 6) * 13 + (wi - wj + 6);
    float v = g_bt[t*NH + h];
    g_rpbT[idx] = 16.0f / (1.0f + __expf(-v));
}

// ---------------------------------------------------------------------------
// A-resident bf16x3 GEMM via mma.sync + cp.async (unchanged from R5)
// ---------------------------------------------------------------------------
#define AROW   528
#define A_MAT  (128 * AROW)
#define BROW   144
#define B_MAT  (128 * BROW)
#define OFF_B  (2 * A_MAT)
#define GEMM_SMEM (2 * A_MAT + 4 * B_MAT)

template<bool IS_QKV>
__global__ __launch_bounds__(256)
void gemm_mma(const __nv_bfloat16* __restrict__ Ah,
              const __nv_bfloat16* __restrict__ Al,
              const __nv_bfloat16* __restrict__ Bh,
              const __nv_bfloat16* __restrict__ Bl,
              float* __restrict__ outp,
              const float* __restrict__ qb,
              const float* __restrict__ vb,
              const float* __restrict__ pb,
              int nTiles)
{
    extern __shared__ __align__(16) unsigned char smc[];
    const uint32_t sb  = smem_u32(smc);
    const uint32_t sAH = sb;
    const uint32_t sAL = sb + A_MAT;

    int tid  = threadIdx.x;
    int lane = tid & 31;
    int wid  = tid >> 5;
    int wm   = wid & 3;
    int wn   = wid >> 2;
    int m0   = blockIdx.x * 128;
    int nIter = nTiles * 4;

    {
        const char* gAh = (const char*)Ah + (size_t)m0 * 512;
        const char* gAl = (const char*)Al + (size_t)m0 * 512;
#pragma unroll
        for (int t = 0; t < 16; t++) {
            int cidx = tid + t * 256;
            int r = cidx >> 5, c = cidx & 31;
            uint32_t so = (uint32_t)r * AROW + (uint32_t)c * 16;
            size_t  go = (size_t)r * 512 + (size_t)c * 16;
            CP16(sAH + so, gAh + go);
            CP16(sAL + so, gAl + go);
        }
    }
    auto issueB = [&](int it, int buf) {
        int nt = it >> 2, ck = it & 3;
        uint32_t bBH = sb + OFF_B + (uint32_t)buf * (2 * B_MAT);
        uint32_t bBL = bBH + B_MAT;
        const char* gBh = (const char*)Bh + (size_t)nt * 128 * 512 + (size_t)ck * 128;
        const char* gBl = (const char*)Bl + (size_t)nt * 128 * 512 + (size_t)ck * 128;
#pragma unroll
        for (int t = 0; t < 4; t++) {
            int cidx = tid + t * 256;
            int r = cidx >> 3, c = cidx & 7;
            uint32_t so = (uint32_t)r * BROW + (uint32_t)c * 16;
            size_t  go = (size_t)r * 512 + (size_t)c * 16;
            CP16(bBH + so, gBh + go);
            CP16(bBL + so, gBl + go);
        }
    };

    issueB(0, 0);
    CP_COMMIT();
    issueB(1, 1);
    CP_COMMIT();
    CP_WAIT1();
    __syncthreads();

    int a_row = wm*32 + (lane & 7) + ((lane >> 3) & 1) * 8;
    int a_chk = (lane >> 4);
    int b_row = wn*64 + (lane & 7) + ((lane >> 4) & 1) * 8;
    int b_chk = (lane >> 3) & 1;

    float acc[2][8][4];
#pragma unroll
    for (int i = 0; i < 2; i++)
#pragma unroll
        for (int j = 0; j < 8; j++)
#pragma unroll
            for (int k = 0; k < 4; k++) acc[i][j][k] = 0.0f;

    const size_t tstride = (size_t)BW * NH * NTOK * HD;

    for (int it = 0; it < nIter; it++) {
        int buf = it & 1;
        int ck  = it & 3;
        uint32_t bBH = sb + OFF_B + (uint32_t)buf * (2 * B_MAT);
        uint32_t bBL = bBH + B_MAT;

#pragma unroll
        for (int kk = 0; kk < 4; kk++) {
            int kkg = ck * 4 + kk;
            uint32_t ah[2][4], al[2][4];
#pragma unroll
            for (int mt = 0; mt < 2; mt++) {
                uint32_t off = (uint32_t)(a_row + mt*16) * AROW
                             + (uint32_t)(a_chk + 2*kkg) * 16;
                ldsm_x4(ah[mt], sAH + off);
                ldsm_x4(al[mt], sAL + off);
            }
            uint32_t bh4[4][4], bl4[4][4];
#pragma unroll
            for (int nn = 0; nn < 4; nn++) {
                uint32_t off = (uint32_t)(b_row + nn*16) * BROW
                             + (uint32_t)(b_chk + 2*kk) * 16;
                ldsm_x4(bh4[nn], bBH + off);
                ldsm_x4(bl4[nn], bBL + off);
            }
#pragma unroll
            for (int mt = 0; mt < 2; mt++)
#pragma unroll
                for (int nt8 = 0; nt8 < 8; nt8++) {
                    int pr = nt8 >> 1, w2 = (nt8 & 1) * 2;
                    mma16816(acc[mt][nt8], ah[mt], bh4[pr][w2], bh4[pr][w2+1]);
                    mma16816(acc[mt][nt8], ah[mt], bl4[pr][w2], bl4[pr][w2+1]);
                    mma16816(acc[mt][nt8], al[mt], bh4[pr][w2], bh4[pr][w2+1]);
                }
        }

        if (ck == 3) {
            int nt = it >> 2;
            int n0 = nt * 128;
#pragma unroll
            for (int mt = 0; mt < 2; mt++) {
                int rA = m0 + wm*32 + mt*16 + (lane >> 2);
#pragma unroll
                for (int nt8 = 0; nt8 < 8; nt8++) {
                    int n = n0 + wn*64 + nt8*8 + (lane & 3) * 2;
                    if (IS_QKV) {
                        int which = n >> 8;
                        int h = (n >> 5) & 7;
                        int d = n & 31;
                        float2 bv = make_float2(0.f, 0.f);
                        if (which == 0)      bv = *(const float2*)(qb + (n & 255));
                        else if (which == 2) bv = *(const float2*)(vb + (n & 255));
                        {
                            int bwin = rA / NTOK, tok = rA - bwin * NTOK;
                            float* dst = g_qkv + (size_t)which * tstride
                                       + (((size_t)bwin * NH + h) * NTOK + tok) * HD + d;
                            *(float2*)dst = make_float2(acc[mt][nt8][0] + bv.x,
                                                        acc[mt][nt8][1] + bv.y);
                        }
                        {
                            int r2 = rA + 8;
                            int bwin = r2 / NTOK, tok = r2 - bwin * NTOK;
                            float* dst = g_qkv + (size_t)which * tstride
                                       + (((size_t)bwin * NH + h) * NTOK + tok) * HD + d;
                            *(float2*)dst = make_float2(acc[mt][nt8][2] + bv.x,
                                                        acc[mt][nt8][3] + bv.y);
                        }
                    } else {
                        float2 bv = *(const float2*)(pb + n);
                        *(float2*)(outp + (size_t)rA * DIM + n) =
                            make_float2(acc[mt][nt8][0] + bv.x, acc[mt][nt8][1] + bv.y);
                        *(float2*)(outp + (size_t)(rA + 8) * DIM + n) =
                            make_float2(acc[mt][nt8][2] + bv.x, acc[mt][nt8][3] + bv.y);
                    }
                    acc[mt][nt8][0] = 0.f; acc[mt][nt8][1] = 0.f;
                    acc[mt][nt8][2] = 0.f; acc[mt][nt8][3] = 0.f;
                }
            }
        }

        if (it + 1 >= nIter) break;
        __syncthreads();
        if (it + 2 < nIter) {
            issueB(it + 2, buf);
            CP_COMMIT();
            CP_WAIT1();
        } else {
            CP_WAIT0();
        }
        __syncthreads();
    }
}

// ---------------------------------------------------------------------------
// fused cosine attention — single-pass online softmax with STATIC max.
// Score s = scale*cos(q,k) + rpb, with cos<=1, rpb in (0,16) => s <= scale+16,
// and the diagonal guarantees true max >= scale, so smax = scale+16 is within
// 16 of the true max: exp(s - smax) in [~e^-48, 1], no overflow/underflow.
// No score buffer => smem = k/v only (28 KB).
// ---------------------------------------------------------------------------
#define QPAD 36
#define ATTN_SMEM (2 * NTOK * QPAD * 4)

__global__ __launch_bounds__(128)
void attn_kernel(const float* __restrict__ logit_scale)
{
    extern __shared__ float sm[];
    float* ks = sm;
    float* vs = sm + NTOK * QPAD;

    int bh = blockIdx.x;
    int b = bh >> 3;
    int h = bh & 7;
    int tid = threadIdx.x;

    const size_t tensor_stride = (size_t)BW * NH * NTOK * HD;
    size_t base = ((size_t)b * NH + h) * (NTOK * HD);
    const float* Q  = g_qkv + base;
    const float* Kp = g_qkv + tensor_stride + base;
    const float* Vp = g_qkv + 2 * tensor_stride + base;
    const float* rpbT_h = g_rpbT + (size_t)h * (NTOK * NTOK);

    for (int idx = tid; idx < NTOK * HD; idx += 128) {
        int r = idx >> 5, d = idx & 31;
        ks[r*QPAD + d] = Kp[idx];
        vs[r*QPAD + d] = Vp[idx];
    }
    __syncthreads();

    float scale = __expf(fminf(logit_scale[h], 4.6051702f));
    float smax = scale + 16.0f;

    int i = tid;
    ull q2[16];
    if (i < NTOK) {
        // q row -> registers, normalized * scale
        const float4* Qr = (const float4*)(Q + (size_t)i * HD);
        float qr[HD];
        float nq = 0.f;
#pragma unroll
        for (int c = 0; c < 8; c++) {
            float4 t = Qr[c];
            qr[c*4+0] = t.x; qr[c*4+1] = t.y; qr[c*4+2] = t.z; qr[c*4+3] = t.w;
            nq += t.x*t.x + t.y*t.y + t.z*t.z + t.w*t.w;
        }
        float rq = scale / fmaxf(sqrtf(nq), 1e-12f);
#pragma unroll
        for (int c = 0; c < 16; c++)
            q2[c] = pack2(qr[c*2] * rq, qr[c*2+1] * rq);

        // normalize k row i in smem
        float nk = 0.f;
#pragma unroll
        for (int d = 0; d < HD; d++) {
            float k = ks[i*QPAD + d];
            nk += k * k;
        }
        float rk = 1.0f / fmaxf(sqrtf(nk), 1e-12f);
#pragma unroll
        for (int c = 0; c < 8; c++) {
            float4 k4 = *(float4*)&ks[i*QPAD + c*4];
            k4.x *= rk; k4.y *= rk; k4.z *= rk; k4.w *= rk;
            *(float4*)&ks[i*QPAD + c*4] = k4;
        }
    }
    __syncthreads();

    if (i < NTOK) {
        float sum = 0.f;
        ull accv2[16];
#pragma unroll
        for (int c = 0; c < 16; c++) accv2[c] = 0ull;

        for (int j = 0; j < NTOK; j++) {
            // dot(q_i, k_j) — k row broadcast across the warp
            const ulonglong2* kr = (const ulonglong2*)(ks + j*QPAD);
            ull s2a = 0ull, s2b = 0ull;
#pragma unroll
            for (int c = 0; c < 8; c += 2) {
                ulonglong2 ka = kr[c];
                ulonglong2 kb = kr[c+1];
                s2a = ffma2(q2[c*2+0], ka.x, s2a);
                s2b = ffma2(q2[c*2+1], ka.y, s2b);
                s2a = ffma2(q2[c*2+2], kb.x, s2a);
                s2b = ffma2(q2[c*2+3], kb.y, s2b);
            }
            float s = lo32(s2a) + hi32(s2a) + lo32(s2b) + hi32(s2b)
                    + rpbT_h[j * NTOK + i];       // coalesced across threads
            float e = __expf(s - smax);
            sum += e;
            ull p2 = pack2(e, e);
            const ulonglong2* vr = (const ulonglong2*)(vs + j*QPAD);
#pragma unroll
            for (int c = 0; c < 8; c++) {
                ulonglong2 v2 = vr[c];
                accv2[c*2+0] = ffma2(p2, v2.x, accv2[c*2+0]);
                accv2[c*2+1] = ffma2(p2, v2.y, accv2[c*2+1]);
            }
        }
        float inv = 1.0f / sum;

        size_t row = ((size_t)b * NTOK + i) * DIM + (size_t)h * HD;
        uint32_t* ohp = (uint32_t*)(g_oh + row);
        uint32_t* olp = (uint32_t*)(g_ol + row);
#pragma unroll
        for (int c = 0; c < 16; c++) {
            float v0 = lo32(accv2[c]) * inv;
            float v1 = hi32(accv2[c]) * inv;
            unsigned short h0, h1, l0, l1;
            split_bf16(v0, h0, l0);
            split_bf16(v1, h1, l1);
            ohp[c] = (uint32_t)h0 | ((uint32_t)h1 << 16);
            olp[c] = (uint32_t)l0 | ((uint32_t)l1 << 16);
        }
    }
}

// ---------------------------------------------------------------------------
// kernel_launch
// ---------------------------------------------------------------------------
extern "C" void kernel_launch(void* const* d_in, const int* in_sizes, int n_in,
                              void* d_out, int out_size)
{
    const float* x           = (const float*)d_in[0];
    const float* qkv_w       = (const float*)d_in[1];
    const float* q_bias      = (const float*)d_in[2];
    const float* v_bias      = (const float*)d_in[3];
    const float* logit_scale = (const float*)d_in[4];
    const float* cpb_w1      = (const float*)d_in[5];
    const float* cpb_b1      = (const float*)d_in[6];
    const float* cpb_w2      = (const float*)d_in[7];
    const float* proj_w      = (const float*)d_in[8];
    const float* proj_b      = (const float*)d_in[9];
    float* out = (float*)d_out;

    __nv_bfloat16 *xh, *xl, *oh, *ol, *wqh, *wql, *wph, *wpl;
    cudaGetSymbolAddress((void**)&xh,  g_xh);
    cudaGetSymbolAddress((void**)&xl,  g_xl);
    cudaGetSymbolAddress((void**)&oh,  g_oh);
    cudaGetSymbolAddress((void**)&ol,  g_ol);
    cudaGetSymbolAddress((void**)&wqh, g_wqh);
    cudaGetSymbolAddress((void**)&wql, g_wql);
    cudaGetSymbolAddress((void**)&wph, g_wph);
    cudaGetSymbolAddress((void**)&wpl, g_wpl);

    static bool attr_set = false;
    if (!attr_set) {
        cudaFuncSetAttribute(attn_kernel,
                             cudaFuncAttributeMaxDynamicSharedMemorySize, ATTN_SMEM);
        cudaFuncSetAttribute(gemm_mma<true>,
                             cudaFuncAttributeMaxDynamicSharedMemorySize, GEMM_SMEM);
        cudaFuncSetAttribute(gemm_mma<false>,
                             cudaFuncAttributeMaxDynamicSharedMemorySize, GEMM_SMEM);
        attr_set = true;
    }

    // 1. split inputs to bf16 hi/lo
    {
        int n4 = (M_ROWS * DIM) / 4;
        cvt_hilo4<<<(n4 + 255) / 256, 256>>>((const float4*)x, (uint2*)xh, (uint2*)xl, n4);
    }
    cvt_hilo4<<<(768 * DIM / 4 + 255) / 256, 256>>>((const float4*)qkv_w,
                                                    (uint2*)wqh, (uint2*)wql, 768 * DIM / 4);
    cvt_hilo4<<<(DIM * DIM / 4 + 255) / 256, 256>>>((const float4*)proj_w,
                                                    (uint2*)wph, (uint2*)wpl, DIM * DIM / 4);

    // 2. CPB bias
    cpb_mlp_kernel<<<(TBL + 7) / 8, 256>>>(cpb_w1, cpb_b1, cpb_w2);
    rpb_kernel<<<(NH * NTOK * NTOK + 255) / 256, 256>>>();

    // 3. QKV GEMM
    gemm_mma<true><<<MTILES, 256, GEMM_SMEM>>>(xh, xl, wqh, wql,
                                               nullptr, q_bias, v_bias, nullptr, 6);

    // 4. fused attention (single-pass, static-max softmax)
    attn_kernel<<<BW * NH, 128, ATTN_SMEM>>>(logit_scale);

    // 5. proj GEMM
    gemm_mma<false><<<MTILES, 256, GEMM_SMEM>>>(oh, ol, wph, wpl,
                                                out, nullptr, nullptr, proj_b, 2);
}